// round 5
// baseline (speedup 1.0000x reference)
#include <cuda_runtime.h>
#include <cuda_bf16.h>
#include <cstdint>

// ---------------------------------------------------------------------------
// SentimentGAT on GB300 (sm_103 baseline PTX): bf16x3 mma.sync GEMMs with
// fused fp32->bf16 hi/lo conversion; unnormalized-scatter attention stack.
// ---------------------------------------------------------------------------

#define GAT_N   30000
#define GAT_Mp  30080               // 235 * 128
#define GAT_E   480000
#define GAT_DIN 5000
#define GAT_K1P 5056                // 79 * 64 (padded K stride for W1^T)
#define GAT_HF  256
#define GAT_F   64

// ---- fp32 scratch ----
__device__ float g_hA[GAT_N * GAT_HF];
__device__ float g_hB[GAT_N * GAT_HF];
__device__ float g_h3[GAT_N * GAT_F];
__device__ float g_acc3[GAT_N * GAT_F];
__device__ float g_es[GAT_N * 4];
__device__ float g_ed[GAT_N * 4];
__device__ float g_den[GAT_N * 4];

// ---- bf16 hi/lo scratch ----
__device__ __align__(128) __nv_bfloat16 g_Ah[(size_t)GAT_Mp * GAT_HF];
__device__ __align__(128) __nv_bfloat16 g_Al[(size_t)GAT_Mp * GAT_HF];
__device__ __align__(128) __nv_bfloat16 g_Bh[256 * GAT_K1P];
__device__ __align__(128) __nv_bfloat16 g_Bl[256 * GAT_K1P];

// ===========================================================================
// low-level helpers
// ===========================================================================
#define SWZ(o) ((o) ^ (((o) >> 3) & 0x70))

__device__ __forceinline__ uint32_t smem_u32(const void* p) {
    uint32_t a;
    asm("{ .reg .u64 t; cvta.to.shared.u64 t, %1; cvt.u32.u64 %0, t; }"
        : "=r"(a) : "l"(p));
    return a;
}
__device__ __forceinline__ void cp16(uint32_t d, const void* s) {
    asm volatile("cp.async.cg.shared.global [%0], [%1], 16;" :: "r"(d), "l"(s));
}
__device__ __forceinline__ void cp16z(uint32_t d, const void* s, bool pred) {
    int sz = pred ? 16 : 0;
    asm volatile("cp.async.cg.shared.global [%0], [%1], 16, %2;"
                 :: "r"(d), "l"(s), "r"(sz));
}
__device__ __forceinline__ void cp_commit() {
    asm volatile("cp.async.commit_group;" ::: "memory");
}
template <int Ng>
__device__ __forceinline__ void cp_wait() {
    asm volatile("cp.async.wait_group %0;" :: "n"(Ng) : "memory");
}
__device__ __forceinline__ void ldsm4(uint32_t (&r)[4], uint32_t addr) {
    asm volatile("ldmatrix.sync.aligned.m8n8.x4.shared.b16 {%0,%1,%2,%3}, [%4];"
                 : "=r"(r[0]), "=r"(r[1]), "=r"(r[2]), "=r"(r[3]) : "r"(addr));
}
__device__ __forceinline__ void mma16816(float (&d)[4], const uint32_t (&a)[4],
                                         uint32_t b0, uint32_t b1) {
    asm volatile("mma.sync.aligned.m16n8k16.row.col.f32.bf16.bf16.f32 "
                 "{%0,%1,%2,%3}, {%4,%5,%6,%7}, {%8,%9}, {%0,%1,%2,%3};"
                 : "+f"(d[0]), "+f"(d[1]), "+f"(d[2]), "+f"(d[3])
                 : "r"(a[0]), "r"(a[1]), "r"(a[2]), "r"(a[3]), "r"(b0), "r"(b1));
}
__device__ __forceinline__ uint32_t bfpack(float a, float b) {
    return (uint32_t)__bfloat16_as_ushort(__float2bfloat16_rn(a)) |
           ((uint32_t)__bfloat16_as_ushort(__float2bfloat16_rn(b)) << 16);
}
__device__ __forceinline__ void red_add_v4(float* addr, float4 v) {
    asm volatile("red.global.add.v4.f32 [%0], {%1,%2,%3,%4};"
                 :: "l"(addr), "f"(v.x), "f"(v.y), "f"(v.z), "f"(v.w) : "memory");
}

// ===========================================================================
// FUSED layer-1 GEMM: C[M,256] = split3(X) @ split3(W1)^T
// blockIdx.x = N-column half (schedule-adjacent -> X rows dedup in L2),
// blockIdx.y = M tile.
// ===========================================================================
__global__ __launch_bounds__(256)
void gemm_fused(const float* __restrict__ X,
                const __nv_bfloat16* __restrict__ Bh, const __nv_bfloat16* __restrict__ Bl,
                float* __restrict__ C, int M, int K, int KpB) {
    constexpr int STAGE = 49152;
    extern __shared__ char smem[];
    const uint32_t sb = smem_u32(smem);

    const int tid = threadIdx.x;
    const int wid = tid >> 5, lane = tid & 31;
    const int wm = wid & 3, wn = wid >> 2;
    const int bm0 = blockIdx.y * 128;
    const int bn0 = blockIdx.x * 128;

    float acc[2][8][4];
#pragma unroll
    for (int i = 0; i < 2; i++)
#pragma unroll
        for (int j = 0; j < 8; j++)
#pragma unroll
            for (int k = 0; k < 4; k++) acc[i][j][k] = 0.f;

    const int NC = (K + 31) >> 5;

    auto load_stage = [&](int c, int stg) {
        const uint32_t base = sb + stg * STAGE;
        const int k0 = c * 32;
#pragma unroll
        for (int t = 0; t < 4; t++) {
            int i = tid + t * 256;
            int row = i >> 3, q = i & 7;
            int gm = bm0 + row, gk = k0 + q * 4;
            bool p = (gm < M) && (gk < K);
            cp16z(base + row * 128 + q * 16, X + (p ? ((size_t)gm * K + gk) : 0), p);
        }
#pragma unroll
        for (int t = 0; t < 4; t++) {
            int i = tid + t * 256;
            int half = i >> 9;
            int rem = i & 511;
            int row = rem >> 2, ch = rem & 3;
            const __nv_bfloat16* src =
                (half ? Bl : Bh) + (size_t)(bn0 + row) * KpB + k0 + ch * 8;
            cp16(base + 32768 + half * 8192 + SWZ(row * 64 + ch * 16), src);
        }
    };

    const int a_row = wm * 32 + (lane & 15);
    const int a_chb = lane >> 4;
    const int b_row = wn * 64 + ((lane >> 4) & 1) * 8 + (lane & 7);
    const int b_chb = (lane >> 3) & 1;

    load_stage(0, 0);
    cp_commit();

    for (int c = 0; c < NC; c++) {
        const int stg = c & 1;
        const uint32_t base = sb + stg * STAGE;
        cp_wait<0>();
        __syncthreads();
#pragma unroll
        for (int t = 0; t < 2; t++) {
            int i = tid + t * 256;
            int row = i >> 2, ch = i & 3;
            const float4* fp = (const float4*)(smem + stg * STAGE + row * 128 + ch * 32);
            float4 v0 = fp[0], v1 = fp[1];
            float f[8] = {v0.x, v0.y, v0.z, v0.w, v1.x, v1.y, v1.z, v1.w};
            uint32_t hi[4], lo[4];
#pragma unroll
            for (int k = 0; k < 4; k++) {
                float h0 = __bfloat162float(__float2bfloat16_rn(f[2 * k]));
                float h1 = __bfloat162float(__float2bfloat16_rn(f[2 * k + 1]));
                hi[k] = bfpack(f[2 * k], f[2 * k + 1]);
                lo[k] = bfpack(f[2 * k] - h0, f[2 * k + 1] - h1);
            }
            uint32_t off = SWZ(row * 64 + ch * 16);
            *(uint4*)(smem + stg * STAGE + 16384 + off) = make_uint4(hi[0], hi[1], hi[2], hi[3]);
            *(uint4*)(smem + stg * STAGE + 24576 + off) = make_uint4(lo[0], lo[1], lo[2], lo[3]);
        }
        __syncthreads();
        if (c + 1 < NC) {
            load_stage(c + 1, stg ^ 1);
            cp_commit();
        }

        const uint32_t aH = base + 16384, aL = base + 24576;
        const uint32_t bH = base + 32768, bL = base + 40960;
#pragma unroll
        for (int ks = 0; ks < 2; ks++) {
            uint32_t ah[2][4], al[2][4];
#pragma unroll
            for (int mf = 0; mf < 2; mf++) {
                uint32_t off = SWZ((a_row + mf * 16) * 64 + (ks * 2 + a_chb) * 16);
                ldsm4(ah[mf], aH + off);
                ldsm4(al[mf], aL + off);
            }
            uint32_t bh[4][4], bl[4][4];
#pragma unroll
            for (int p = 0; p < 4; p++) {
                uint32_t off = SWZ((b_row + p * 16) * 64 + (ks * 2 + b_chb) * 16);
                ldsm4(bh[p], bH + off);
                ldsm4(bl[p], bL + off);
            }
#pragma unroll
            for (int mf = 0; mf < 2; mf++)
#pragma unroll
                for (int p = 0; p < 4; p++) {
                    mma16816(acc[mf][2 * p],     ah[mf], bh[p][0], bh[p][1]);
                    mma16816(acc[mf][2 * p],     ah[mf], bl[p][0], bl[p][1]);
                    mma16816(acc[mf][2 * p],     al[mf], bh[p][0], bh[p][1]);
                    mma16816(acc[mf][2 * p + 1], ah[mf], bh[p][2], bh[p][3]);
                    mma16816(acc[mf][2 * p + 1], ah[mf], bl[p][2], bl[p][3]);
                    mma16816(acc[mf][2 * p + 1], al[mf], bh[p][2], bh[p][3]);
                }
        }
    }

#pragma unroll
    for (int mf = 0; mf < 2; mf++) {
        int r0 = bm0 + wm * 32 + mf * 16 + (lane >> 2);
#pragma unroll
        for (int nf = 0; nf < 8; nf++) {
            int col = bn0 + wn * 64 + nf * 8 + (lane & 3) * 2;
            if (r0 < M)
                *(float2*)(C + (size_t)r0 * 256 + col) =
                    make_float2(acc[mf][nf][0], acc[mf][nf][1]);
            if (r0 + 8 < M)
                *(float2*)(C + (size_t)(r0 + 8) * 256 + col) =
                    make_float2(acc[mf][nf][2], acc[mf][nf][3]);
        }
    }
}

// ===========================================================================
// pre-split GEMM for layers 2/3. blockIdx.y = M tile, blockIdx.x = N block.
// ===========================================================================
template <int BN>
__global__ __launch_bounds__(256)
void gemm_mma(const __nv_bfloat16* __restrict__ Ah, const __nv_bfloat16* __restrict__ Al,
              const __nv_bfloat16* __restrict__ Bh, const __nv_bfloat16* __restrict__ Bl,
              float* __restrict__ C, int M, int N, int Kp) {
    constexpr int WNCOL = BN / 2;
    constexpr int NFRAG = WNCOL / 8;
    constexpr int NPAIR = NFRAG / 2;
    constexpr int ABH = 8192;
    constexpr int BBH = BN * 64;
    constexpr int STAGE = 2 * ABH + 2 * BBH;

    extern __shared__ char smem[];
    const uint32_t sb = smem_u32(smem);

    const int tid = threadIdx.x;
    const int wid = tid >> 5, lane = tid & 31;
    const int wm = wid & 3, wn = wid >> 2;
    const int bm0 = blockIdx.y * 128;
    const int bn0 = blockIdx.x * BN;

    float acc[2][NFRAG][4];
#pragma unroll
    for (int i = 0; i < 2; i++)
#pragma unroll
        for (int j = 0; j < NFRAG; j++)
#pragma unroll
            for (int k = 0; k < 4; k++) acc[i][j][k] = 0.f;

    const int NC = Kp >> 5;

    auto load_stage = [&](int c, int stg) {
        const uint32_t base = sb + stg * STAGE;
        const size_t koff = (size_t)c * 32;
#pragma unroll
        for (int t = 0; t < 4; t++) {
            int i = tid + t * 256;
            int half = i >> 9;
            int rem = i & 511;
            int row = rem >> 2, ch = rem & 3;
            const __nv_bfloat16* src =
                (half ? Al : Ah) + (size_t)(bm0 + row) * Kp + koff + ch * 8;
            cp16(base + half * ABH + SWZ(row * 64 + ch * 16), src);
        }
#pragma unroll
        for (int t = 0; t < BN / 32; t++) {
            int i = tid + t * 256;
            int half = i / (BN * 4);
            int rem = i % (BN * 4);
            int row = rem >> 2, ch = rem & 3;
            const __nv_bfloat16* src =
                (half ? Bl : Bh) + (size_t)(bn0 + row) * Kp + koff + ch * 8;
            cp16(base + 2 * ABH + half * BBH + SWZ(row * 64 + ch * 16), src);
        }
    };

    const int a_row = wm * 32 + (lane & 15);
    const int a_chb = lane >> 4;
    const int b_row = wn * WNCOL + ((lane >> 4) & 1) * 8 + (lane & 7);
    const int b_chb = (lane >> 3) & 1;

    load_stage(0, 0);
    cp_commit();

    for (int c = 0; c < NC; c++) {
        if (c + 1 < NC) {
            load_stage(c + 1, (c + 1) & 1);
            cp_commit();
            cp_wait<1>();
        } else {
            cp_wait<0>();
        }
        __syncthreads();

        const uint32_t base = sb + (c & 1) * STAGE;
        const uint32_t aH = base, aL = base + ABH;
        const uint32_t bH = base + 2 * ABH, bL = bH + BBH;

#pragma unroll
        for (int ks = 0; ks < 2; ks++) {
            uint32_t ah[2][4], al[2][4];
#pragma unroll
            for (int mf = 0; mf < 2; mf++) {
                uint32_t off = SWZ((a_row + mf * 16) * 64 + (ks * 2 + a_chb) * 16);
                ldsm4(ah[mf], aH + off);
                ldsm4(al[mf], aL + off);
            }
            uint32_t bh[NPAIR][4], bl[NPAIR][4];
#pragma unroll
            for (int p = 0; p < NPAIR; p++) {
                uint32_t off = SWZ((b_row + p * 16) * 64 + (ks * 2 + b_chb) * 16);
                ldsm4(bh[p], bH + off);
                ldsm4(bl[p], bL + off);
            }
#pragma unroll
            for (int mf = 0; mf < 2; mf++)
#pragma unroll
                for (int p = 0; p < NPAIR; p++) {
                    mma16816(acc[mf][2 * p],     ah[mf], bh[p][0], bh[p][1]);
                    mma16816(acc[mf][2 * p],     ah[mf], bl[p][0], bl[p][1]);
                    mma16816(acc[mf][2 * p],     al[mf], bh[p][0], bh[p][1]);
                    mma16816(acc[mf][2 * p + 1], ah[mf], bh[p][2], bh[p][3]);
                    mma16816(acc[mf][2 * p + 1], ah[mf], bl[p][2], bl[p][3]);
                    mma16816(acc[mf][2 * p + 1], al[mf], bh[p][2], bh[p][3]);
                }
        }
        __syncthreads();
    }

#pragma unroll
    for (int mf = 0; mf < 2; mf++) {
        int r0 = bm0 + wm * 32 + mf * 16 + (lane >> 2);
#pragma unroll
        for (int nf = 0; nf < NFRAG; nf++) {
            int col = bn0 + wn * WNCOL + nf * 8 + (lane & 3) * 2;
            if (r0 < M)
                *(float2*)(C + (size_t)r0 * N + col) =
                    make_float2(acc[mf][nf][0], acc[mf][nf][1]);
            if (r0 + 8 < M)
                *(float2*)(C + (size_t)(r0 + 8) * N + col) =
                    make_float2(acc[mf][nf][2], acc[mf][nf][3]);
        }
    }
}

// ===========================================================================
// node_prep: per node, compute es/ed logits, self-loop weight w,
// write acc = w*h (initializes accumulator) and den = w.
// ===========================================================================
__global__ void node_prep4(const float* __restrict__ h,
                           const float* __restrict__ a_src,
                           const float* __restrict__ a_dst,
                           float* __restrict__ es, float* __restrict__ ed,
                           float* __restrict__ acc, float* __restrict__ den, int n) {
    int w = (blockIdx.x * blockDim.x + threadIdx.x) >> 5;
    int lane = threadIdx.x & 31;
    if (w >= n) return;
    int c = lane * 8;
    const float* hp = h + (size_t)w * 256 + c;
    float4 v0 = *(const float4*)(hp);
    float4 v1 = *(const float4*)(hp + 4);
    float4 as0 = *(const float4*)(a_src + c);
    float4 as1 = *(const float4*)(a_src + c + 4);
    float4 ad0 = *(const float4*)(a_dst + c);
    float4 ad1 = *(const float4*)(a_dst + c + 4);
    float s = v0.x * as0.x + v0.y * as0.y + v0.z * as0.z + v0.w * as0.w +
              v1.x * as1.x + v1.y * as1.y + v1.z * as1.z + v1.w * as1.w;
    float d = v0.x * ad0.x + v0.y * ad0.y + v0.z * ad0.z + v0.w * ad0.w +
              v1.x * ad1.x + v1.y * ad1.y + v1.z * ad1.z + v1.w * ad1.w;
#pragma unroll
    for (int o = 4; o; o >>= 1) {          // reduce within 8-lane head groups
        s += __shfl_xor_sync(0xffffffffu, s, o);
        d += __shfl_xor_sync(0xffffffffu, d, o);
    }
    float e = s + d;
    e = e > 0.f ? e : 0.2f * e;
    float wx = __expf(e);
    float* ap = acc + (size_t)w * 256 + c;
    v0.x *= wx; v0.y *= wx; v0.z *= wx; v0.w *= wx;
    v1.x *= wx; v1.y *= wx; v1.z *= wx; v1.w *= wx;
    *(float4*)(ap) = v0;
    *(float4*)(ap + 4) = v1;
    if ((lane & 7) == 0) {
        int head = lane >> 3;
        es[w * 4 + head] = s;
        ed[w * 4 + head] = d;
        den[w * 4 + head] = wx;
    }
}

__global__ void node_prep1(const float* __restrict__ h,
                           const float* __restrict__ a_src,
                           const float* __restrict__ a_dst,
                           float* __restrict__ es, float* __restrict__ ed,
                           float* __restrict__ acc, float* __restrict__ den, int n) {
    int w = (blockIdx.x * blockDim.x + threadIdx.x) >> 5;
    int lane = threadIdx.x & 31;
    if (w >= n) return;
    int c = lane * 2;
    float2 v = *(const float2*)(h + (size_t)w * 64 + c);
    float2 as = *(const float2*)(a_src + c);
    float2 ad = *(const float2*)(a_dst + c);
    float s = v.x * as.x + v.y * as.y;
    float d = v.x * ad.x + v.y * ad.y;
#pragma unroll
    for (int o = 16; o; o >>= 1) {
        s += __shfl_xor_sync(0xffffffffu, s, o);
        d += __shfl_xor_sync(0xffffffffu, d, o);
    }
    float e = s + d;
    e = e > 0.f ? e : 0.2f * e;
    float wx = __expf(e);
    *(float2*)(acc + (size_t)w * 64 + c) = make_float2(v.x * wx, v.y * wx);
    if (lane == 0) { es[w] = s; ed[w] = d; den[w] = wx; }
}

// ===========================================================================
// agg_fused: per real edge, w = exp(leaky(es[src]+ed[dst])); scatter
// w*h[src] into acc[dst] and w into den[dst] (atomics).
// ===========================================================================
__global__ void agg_fused4(const int* __restrict__ src, const int* __restrict__ dst,
                           int E_, const float* __restrict__ es,
                           const float* __restrict__ ed,
                           const float* __restrict__ h,
                           float* __restrict__ acc, float* __restrict__ den) {
    int w = (blockIdx.x * blockDim.x + threadIdx.x) >> 5;
    int lane = threadIdx.x & 31;
    if (w >= E_) return;
    int s = src[w], d = dst[w];
    float wv = 0.f;
    if (lane < 4) {
        float e = es[s * 4 + lane] + ed[d * 4 + lane];
        e = e > 0.f ? e : 0.2f * e;
        wv = __expf(e);
    }
    const float* hp = h + (size_t)s * 256;
    float* ap = acc + (size_t)d * 256;
#pragma unroll
    for (int c = lane * 4; c < 256; c += 128) {
        float alpha = __shfl_sync(0xffffffffu, wv, c >> 6);
        float4 v = *(const float4*)(hp + c);
        v.x *= alpha; v.y *= alpha; v.z *= alpha; v.w *= alpha;
        red_add_v4(ap + c, v);
    }
    if (lane == 0) {
        float w1 = __shfl_sync(0xffffffffu, wv, 1);
        float w2 = __shfl_sync(0xffffffffu, wv, 2);
        float w3 = __shfl_sync(0xffffffffu, wv, 3);
        red_add_v4(den + d * 4, make_float4(wv, w1, w2, w3));
    } else if (lane < 4) {
        __shfl_sync(0xffffffffu, wv, 1);
        __shfl_sync(0xffffffffu, wv, 2);
        __shfl_sync(0xffffffffu, wv, 3);
    } else {
        __shfl_sync(0xffffffffu, wv, 1);
        __shfl_sync(0xffffffffu, wv, 2);
        __shfl_sync(0xffffffffu, wv, 3);
    }
}

__global__ void agg_fused1(const int* __restrict__ src, const int* __restrict__ dst,
                           int E_, const float* __restrict__ es,
                           const float* __restrict__ ed,
                           const float* __restrict__ h,
                           float* __restrict__ acc, float* __restrict__ den) {
    int w = (blockIdx.x * blockDim.x + threadIdx.x) >> 5;
    int lane = threadIdx.x & 31;
    if (w >= E_) return;
    int s = src[w], d = dst[w];
    float e = es[s] + ed[d];
    e = e > 0.f ? e : 0.2f * e;
    float wv = __expf(e);
    if (lane < 16) {
        int c = lane * 4;
        float4 v = *(const float4*)(h + (size_t)s * 64 + c);
        v.x *= wv; v.y *= wv; v.z *= wv; v.w *= wv;
        red_add_v4(acc + (size_t)d * 64 + c, v);
    } else if (lane == 16) {
        atomicAdd(den + d, wv);
    }
}

// ===========================================================================
// normalize + bias + ELU + hi/lo split (K fixed 256)
// ===========================================================================
__global__ void conv_split_be(const float* __restrict__ X, const float* __restrict__ den,
                              const float* __restrict__ b,
                              __nv_bfloat16* __restrict__ Hh,
                              __nv_bfloat16* __restrict__ Hl, int M, int Mp) {
    int idx = blockIdx.x * blockDim.x + threadIdx.x;
    if (idx >= Mp * 64) return;
    int row = idx >> 6, q = idx & 63;
    float4 v = make_float4(0.f, 0.f, 0.f, 0.f);
    if (row < M) {
        v = *(const float4*)(X + (size_t)row * 256 + q * 4);
        float dn = den[row * 4 + (q >> 4)];
        float inv = __fdividef(1.f, dn);
        float4 bb = *(const float4*)(b + q * 4);
        v.x = v.x * inv + bb.x; v.y = v.y * inv + bb.y;
        v.z = v.z * inv + bb.z; v.w = v.w * inv + bb.w;
        v.x = v.x > 0.f ? v.x : expm1f(v.x);
        v.y = v.y > 0.f ? v.y : expm1f(v.y);
        v.z = v.z > 0.f ? v.z : expm1f(v.z);
        v.w = v.w > 0.f ? v.w : expm1f(v.w);
    }
    float f[4] = {v.x, v.y, v.z, v.w};
    __nv_bfloat16 h[4], l[4];
#pragma unroll
    for (int j = 0; j < 4; j++) {
        h[j] = __float2bfloat16_rn(f[j]);
        l[j] = __float2bfloat16_rn(f[j] - __bfloat162float(h[j]));
    }
    size_t o = (size_t)row * 256 + q * 4;
    *(__nv_bfloat162*)(Hh + o)     = __nv_bfloat162(h[0], h[1]);
    *(__nv_bfloat162*)(Hh + o + 2) = __nv_bfloat162(h[2], h[3]);
    *(__nv_bfloat162*)(Hl + o)     = __nv_bfloat162(l[0], l[1]);
    *(__nv_bfloat162*)(Hl + o + 2) = __nv_bfloat162(l[2], l[3]);
}

// W [K,N] fp32 -> hi/lo bf16 [N,Kp]
__global__ void conv_wT(const float* __restrict__ W,
                        __nv_bfloat16* __restrict__ Bh,
                        __nv_bfloat16* __restrict__ Bl,
                        int K, int N, int Kp) {
    int idx = blockIdx.x * blockDim.x + threadIdx.x;
    if (idx >= N * Kp) return;
    int n = idx / Kp, k = idx - n * Kp;
    float v = (k < K) ? W[(size_t)k * N + n] : 0.f;
    __nv_bfloat16 h = __float2bfloat16_rn(v);
    __nv_bfloat16 l = __float2bfloat16_rn(v - __bfloat162float(h));
    Bh[(size_t)n * Kp + k] = h;
    Bl[(size_t)n * Kp + k] = l;
}

// ===========================================================================
// final: v = elu(acc/den + b3); out = v @ Wc + bc  (one warp per node)
// ===========================================================================
__global__ void final_cls(const float* __restrict__ acc, const float* __restrict__ den,
                          const float* __restrict__ b3,
                          const float* __restrict__ Wc, const float* __restrict__ bc,
                          float* __restrict__ out, int n) {
    int w = (blockIdx.x * blockDim.x + threadIdx.x) >> 5;
    int lane = threadIdx.x & 31;
    if (w >= n) return;
    float inv = __fdividef(1.f, den[w]);
    float v0 = acc[(size_t)w * 64 + lane] * inv + b3[lane];
    v0 = v0 > 0.f ? v0 : expm1f(v0);
    float v1 = acc[(size_t)w * 64 + lane + 32] * inv + b3[lane + 32];
    v1 = v1 > 0.f ? v1 : expm1f(v1);
#pragma unroll
    for (int j = 0; j < 3; j++) {
        float p = v0 * Wc[lane * 3 + j] + v1 * Wc[(lane + 32) * 3 + j];
#pragma unroll
        for (int o = 16; o; o >>= 1) p += __shfl_xor_sync(0xffffffffu, p, o);
        if (lane == 0) out[w * 3 + j] = p + bc[j];
    }
}

// ===========================================================================
static inline int cdiv(int a, int b) { return (a + b - 1) / b; }

extern "C" void kernel_launch(void* const* d_in, const int* in_sizes, int n_in,
                              void* d_out, int out_size) {
    const float* x    = (const float*)d_in[0];
    const float* W1   = (const float*)d_in[1];
    const float* a1s  = (const float*)d_in[2];
    const float* a1d  = (const float*)d_in[3];
    const float* b1   = (const float*)d_in[4];
    const float* W2   = (const float*)d_in[5];
    const float* a2s  = (const float*)d_in[6];
    const float* a2d  = (const float*)d_in[7];
    const float* b2   = (const float*)d_in[8];
    const float* W3   = (const float*)d_in[9];
    const float* a3s  = (const float*)d_in[10];
    const float* a3d  = (const float*)d_in[11];
    const float* b3   = (const float*)d_in[12];
    const float* Wc   = (const float*)d_in[13];
    const float* bc   = (const float*)d_in[14];
    const int*   ei   = (const int*)d_in[15];
    float* out = (float*)d_out;

    const int N = GAT_N, E = GAT_E, Mp = GAT_Mp;
    const int* src = ei;
    const int* dst = ei + E;

    float *hA, *hB, *h3, *acc3, *es, *ed, *den;
    __nv_bfloat16 *Ahp, *Alp, *Bhp, *Blp;
    cudaGetSymbolAddress((void**)&hA,   g_hA);
    cudaGetSymbolAddress((void**)&hB,   g_hB);
    cudaGetSymbolAddress((void**)&h3,   g_h3);
    cudaGetSymbolAddress((void**)&acc3, g_acc3);
    cudaGetSymbolAddress((void**)&es,   g_es);
    cudaGetSymbolAddress((void**)&ed,   g_ed);
    cudaGetSymbolAddress((void**)&den,  g_den);
    cudaGetSymbolAddress((void**)&Ahp,  g_Ah);
    cudaGetSymbolAddress((void**)&Alp,  g_Al);
    cudaGetSymbolAddress((void**)&Bhp,  g_Bh);
    cudaGetSymbolAddress((void**)&Blp,  g_Bl);

    const int SMF   = 2 * 49152;
    const int SM128 = 2 * (2 * 8192 + 2 * 128 * 64);
    const int SM64  = 2 * (2 * 8192 + 2 * 64 * 64);
    cudaFuncSetAttribute(gemm_fused,    cudaFuncAttributeMaxDynamicSharedMemorySize, SMF);
    cudaFuncSetAttribute(gemm_mma<128>, cudaFuncAttributeMaxDynamicSharedMemorySize, SM128);
    cudaFuncSetAttribute(gemm_mma<64>,  cudaFuncAttributeMaxDynamicSharedMemorySize, SM64);

    const int TB = 256;
    const int MT = Mp / 128;   // 235
    const int NPB = cdiv(N * 32, TB);     // node_prep blocks
    const int AGB = cdiv(E * 32, TB);     // agg blocks

    // ---------------- layer 1 (H=4, K=5000) ----------------
    conv_wT<<<cdiv(256 * GAT_K1P, TB), TB>>>(W1, Bhp, Blp, GAT_DIN, 256, GAT_K1P);
    gemm_fused<<<dim3(2, MT), 256, SMF>>>(x, Bhp, Blp, hA, N, GAT_DIN, GAT_K1P);
    node_prep4<<<NPB, TB>>>(hA, a1s, a1d, es, ed, hB, den, N);
    agg_fused4<<<AGB, TB>>>(src, dst, E, es, ed, hA, hB, den);

    // ---------------- layer 2 (H=4, K=256) ----------------
    conv_split_be<<<cdiv(Mp * 64, TB), TB>>>(hB, den, b1, Ahp, Alp, N, Mp);
    conv_wT<<<cdiv(256 * 256, TB), TB>>>(W2, Bhp, Blp, 256, 256, 256);
    gemm_mma<128><<<dim3(2, MT), 256, SM128>>>(Ahp, Alp, Bhp, Blp, hA, N, 256, 256);
    node_prep4<<<NPB, TB>>>(hA, a2s, a2d, es, ed, hB, den, N);
    agg_fused4<<<AGB, TB>>>(src, dst, E, es, ed, hA, hB, den);

    // ---------------- layer 3 (H=1, K=256, N=64) ----------------
    conv_split_be<<<cdiv(Mp * 64, TB), TB>>>(hB, den, b2, Ahp, Alp, N, Mp);
    conv_wT<<<cdiv(64 * 256, TB), TB>>>(W3, Bhp, Blp, 256, 64, 256);
    gemm_mma<64><<<dim3(1, MT), 256, SM64>>>(Ahp, Alp, Bhp, Blp, h3, N, 64, 256);
    node_prep1<<<NPB, TB>>>(h3, a3s, a3d, es, ed, acc3, den, N);
    agg_fused1<<<AGB, TB>>>(src, dst, E, es, ed, h3, acc3, den);
    final_cls<<<NPB, TB>>>(acc3, den, b3, Wc, bc, out, N);
}

// round 6
// speedup vs baseline: 1.0339x; 1.0339x over previous
#include <cuda_runtime.h>
#include <cuda_bf16.h>
#include <cstdint>

// ---------------------------------------------------------------------------
// SentimentGAT on GB300 (sm_103 baseline PTX): bf16x3 mma.sync GEMMs with
// fused fp32->bf16 hi/lo conversion; unnormalized-scatter attention stack.
// ---------------------------------------------------------------------------

#define GAT_N   30000
#define GAT_Mp  30080               // 235 * 128
#define GAT_E   480000
#define GAT_DIN 5000
#define GAT_K1P 5056                // 79 * 64 (padded K stride for W1^T)
#define GAT_HF  256
#define GAT_F   64

// ---- fp32 scratch ----
__device__ float g_hA[GAT_N * GAT_HF];
__device__ float g_hB[GAT_N * GAT_HF];
__device__ float g_h3[GAT_N * GAT_F];
__device__ float g_acc3[GAT_N * GAT_F];
__device__ float g_es[GAT_N * 4];
__device__ float g_ed[GAT_N * 4];
__device__ float g_den[GAT_N * 4];

// ---- bf16 hi/lo scratch ----
__device__ __align__(128) __nv_bfloat16 g_Ah[(size_t)GAT_Mp * GAT_HF];
__device__ __align__(128) __nv_bfloat16 g_Al[(size_t)GAT_Mp * GAT_HF];
__device__ __align__(128) __nv_bfloat16 g_Bh[256 * GAT_K1P];
__device__ __align__(128) __nv_bfloat16 g_Bl[256 * GAT_K1P];

// ===========================================================================
// low-level helpers
// ===========================================================================
#define SWZ(o) ((o) ^ (((o) >> 3) & 0x70))

__device__ __forceinline__ uint32_t smem_u32(const void* p) {
    uint32_t a;
    asm("{ .reg .u64 t; cvta.to.shared.u64 t, %1; cvt.u32.u64 %0, t; }"
        : "=r"(a) : "l"(p));
    return a;
}
__device__ __forceinline__ void cp16(uint32_t d, const void* s) {
    asm volatile("cp.async.cg.shared.global [%0], [%1], 16;" :: "r"(d), "l"(s));
}
__device__ __forceinline__ void cp_commit() {
    asm volatile("cp.async.commit_group;" ::: "memory");
}
template <int Ng>
__device__ __forceinline__ void cp_wait() {
    asm volatile("cp.async.wait_group %0;" :: "n"(Ng) : "memory");
}
__device__ __forceinline__ void ldsm4(uint32_t (&r)[4], uint32_t addr) {
    asm volatile("ldmatrix.sync.aligned.m8n8.x4.shared.b16 {%0,%1,%2,%3}, [%4];"
                 : "=r"(r[0]), "=r"(r[1]), "=r"(r[2]), "=r"(r[3]) : "r"(addr));
}
__device__ __forceinline__ void mma16816(float (&d)[4], const uint32_t (&a)[4],
                                         uint32_t b0, uint32_t b1) {
    asm volatile("mma.sync.aligned.m16n8k16.row.col.f32.bf16.bf16.f32 "
                 "{%0,%1,%2,%3}, {%4,%5,%6,%7}, {%8,%9}, {%0,%1,%2,%3};"
                 : "+f"(d[0]), "+f"(d[1]), "+f"(d[2]), "+f"(d[3])
                 : "r"(a[0]), "r"(a[1]), "r"(a[2]), "r"(a[3]), "r"(b0), "r"(b1));
}
__device__ __forceinline__ uint32_t bfpack(float a, float b) {
    return (uint32_t)__bfloat16_as_ushort(__float2bfloat16_rn(a)) |
           ((uint32_t)__bfloat16_as_ushort(__float2bfloat16_rn(b)) << 16);
}
__device__ __forceinline__ void red_add_v4(float* addr, float4 v) {
    asm volatile("red.global.add.v4.f32 [%0], {%1,%2,%3,%4};"
                 :: "l"(addr), "f"(v.x), "f"(v.y), "f"(v.z), "f"(v.w) : "memory");
}

// ===========================================================================
// FUSED layer-1 GEMM: C[M,256] = split3(X) @ split3(W1)^T
// X staged via LDG->regs->convert->STS (no fp32 smem staging).
// blockIdx.x = N-column half (schedule-adjacent), blockIdx.y = M tile.
// Stage: AH 8K | AL 8K | BH 8K | BL 8K = 32768 B, two stages.
// ===========================================================================
__global__ __launch_bounds__(256)
void gemm_fused(const float* __restrict__ X,
                const __nv_bfloat16* __restrict__ Bh, const __nv_bfloat16* __restrict__ Bl,
                float* __restrict__ C, int M, int K, int KpB) {
    constexpr int STAGE = 32768;
    extern __shared__ char smem[];
    const uint32_t sb = smem_u32(smem);

    const int tid = threadIdx.x;
    const int wid = tid >> 5, lane = tid & 31;
    const int wm = wid & 3, wn = wid >> 2;
    const int bm0 = blockIdx.y * 128;
    const int bn0 = blockIdx.x * 128;

    float acc[2][8][4];
#pragma unroll
    for (int i = 0; i < 2; i++)
#pragma unroll
        for (int j = 0; j < 8; j++)
#pragma unroll
            for (int k = 0; k < 4; k++) acc[i][j][k] = 0.f;

    const int NC = (K + 31) >> 5;

    // X tile registers: 2 chunks x 8 floats (row = i>>2, ch = i&3)
    float4 xr[2][2];
    auto ldg_x = [&](int c) {
#pragma unroll
        for (int t = 0; t < 2; t++) {
            int i = tid + t * 256;
            int row = i >> 2, ch = i & 3;
            int gm = bm0 + row, gk = c * 32 + ch * 8;
            if (gm < M && gk + 8 <= K) {   // K % 8 == 0 -> chunk all-or-nothing
                const float4* g = (const float4*)(X + (size_t)gm * K + gk);
                xr[t][0] = g[0];
                xr[t][1] = g[1];
            } else {
                xr[t][0] = make_float4(0.f, 0.f, 0.f, 0.f);
                xr[t][1] = make_float4(0.f, 0.f, 0.f, 0.f);
            }
        }
    };
    auto sts_convert = [&](int stg) {
#pragma unroll
        for (int t = 0; t < 2; t++) {
            int i = tid + t * 256;
            int row = i >> 2, ch = i & 3;
            float f[8] = {xr[t][0].x, xr[t][0].y, xr[t][0].z, xr[t][0].w,
                          xr[t][1].x, xr[t][1].y, xr[t][1].z, xr[t][1].w};
            uint32_t hi[4], lo[4];
#pragma unroll
            for (int k = 0; k < 4; k++) {
                float h0 = __bfloat162float(__float2bfloat16_rn(f[2 * k]));
                float h1 = __bfloat162float(__float2bfloat16_rn(f[2 * k + 1]));
                hi[k] = bfpack(f[2 * k], f[2 * k + 1]);
                lo[k] = bfpack(f[2 * k] - h0, f[2 * k + 1] - h1);
            }
            uint32_t off = SWZ(row * 64 + ch * 16);
            *(uint4*)(smem + stg * STAGE + off)        = make_uint4(hi[0], hi[1], hi[2], hi[3]);
            *(uint4*)(smem + stg * STAGE + 8192 + off) = make_uint4(lo[0], lo[1], lo[2], lo[3]);
        }
    };
    auto ldb = [&](int c, int stg) {
        const uint32_t base = sb + stg * STAGE + 16384;
        const int k0 = c * 32;
#pragma unroll
        for (int t = 0; t < 4; t++) {
            int i = tid + t * 256;
            int half = i >> 9;
            int rem = i & 511;
            int row = rem >> 2, ch = rem & 3;
            const __nv_bfloat16* src =
                (half ? Bl : Bh) + (size_t)(bn0 + row) * KpB + k0 + ch * 8;
            cp16(base + half * 8192 + SWZ(row * 64 + ch * 16), src);
        }
    };

    const int a_row = wm * 32 + (lane & 15);
    const int a_chb = lane >> 4;
    const int b_row = wn * 64 + ((lane >> 4) & 1) * 8 + (lane & 7);
    const int b_chb = (lane >> 3) & 1;

    ldg_x(0);
    ldb(0, 0);
    cp_commit();

    for (int c = 0; c < NC; c++) {
        const int stg = c & 1;
        const uint32_t base = sb + stg * STAGE;

        sts_convert(stg);            // safe: stage stg last read 2 barriers ago
        cp_wait<0>();                // B(c) resident
        __syncthreads();             // orders STS + cp.async vs ldmatrix

        if (c + 1 < NC) {            // prefetch next tile during mma
            ldg_x(c + 1);
            ldb(c + 1, stg ^ 1);     // stage stg^1 reads finished before barrier
            cp_commit();
        }

        const uint32_t aH = base, aL = base + 8192;
        const uint32_t bH = base + 16384, bL = base + 24576;
#pragma unroll
        for (int ks = 0; ks < 2; ks++) {
            uint32_t ah[2][4], al[2][4];
#pragma unroll
            for (int mf = 0; mf < 2; mf++) {
                uint32_t off = SWZ((a_row + mf * 16) * 64 + (ks * 2 + a_chb) * 16);
                ldsm4(ah[mf], aH + off);
                ldsm4(al[mf], aL + off);
            }
            uint32_t bh[4][4], bl[4][4];
#pragma unroll
            for (int p = 0; p < 4; p++) {
                uint32_t off = SWZ((b_row + p * 16) * 64 + (ks * 2 + b_chb) * 16);
                ldsm4(bh[p], bH + off);
                ldsm4(bl[p], bL + off);
            }
#pragma unroll
            for (int mf = 0; mf < 2; mf++)
#pragma unroll
                for (int p = 0; p < 4; p++) {
                    mma16816(acc[mf][2 * p],     ah[mf], bh[p][0], bh[p][1]);
                    mma16816(acc[mf][2 * p],     ah[mf], bl[p][0], bl[p][1]);
                    mma16816(acc[mf][2 * p],     al[mf], bh[p][0], bh[p][1]);
                    mma16816(acc[mf][2 * p + 1], ah[mf], bh[p][2], bh[p][3]);
                    mma16816(acc[mf][2 * p + 1], ah[mf], bl[p][2], bl[p][3]);
                    mma16816(acc[mf][2 * p + 1], al[mf], bh[p][2], bh[p][3]);
                }
        }
    }

#pragma unroll
    for (int mf = 0; mf < 2; mf++) {
        int r0 = bm0 + wm * 32 + mf * 16 + (lane >> 2);
#pragma unroll
        for (int nf = 0; nf < 8; nf++) {
            int col = bn0 + wn * 64 + nf * 8 + (lane & 3) * 2;
            if (r0 < M)
                *(float2*)(C + (size_t)r0 * 256 + col) =
                    make_float2(acc[mf][nf][0], acc[mf][nf][1]);
            if (r0 + 8 < M)
                *(float2*)(C + (size_t)(r0 + 8) * 256 + col) =
                    make_float2(acc[mf][nf][2], acc[mf][nf][3]);
        }
    }
}

// ===========================================================================
// pre-split GEMM for layers 2/3 (unchanged, proven)
// ===========================================================================
template <int BN>
__global__ __launch_bounds__(256)
void gemm_mma(const __nv_bfloat16* __restrict__ Ah, const __nv_bfloat16* __restrict__ Al,
              const __nv_bfloat16* __restrict__ Bh, const __nv_bfloat16* __restrict__ Bl,
              float* __restrict__ C, int M, int N, int Kp) {
    constexpr int WNCOL = BN / 2;
    constexpr int NFRAG = WNCOL / 8;
    constexpr int NPAIR = NFRAG / 2;
    constexpr int ABH = 8192;
    constexpr int BBH = BN * 64;
    constexpr int STAGE = 2 * ABH + 2 * BBH;

    extern __shared__ char smem[];
    const uint32_t sb = smem_u32(smem);

    const int tid = threadIdx.x;
    const int wid = tid >> 5, lane = tid & 31;
    const int wm = wid & 3, wn = wid >> 2;
    const int bm0 = blockIdx.y * 128;
    const int bn0 = blockIdx.x * BN;

    float acc[2][NFRAG][4];
#pragma unroll
    for (int i = 0; i < 2; i++)
#pragma unroll
        for (int j = 0; j < NFRAG; j++)
#pragma unroll
            for (int k = 0; k < 4; k++) acc[i][j][k] = 0.f;

    const int NC = Kp >> 5;

    auto load_stage = [&](int c, int stg) {
        const uint32_t base = sb + stg * STAGE;
        const size_t koff = (size_t)c * 32;
#pragma unroll
        for (int t = 0; t < 4; t++) {
            int i = tid + t * 256;
            int half = i >> 9;
            int rem = i & 511;
            int row = rem >> 2, ch = rem & 3;
            const __nv_bfloat16* src =
                (half ? Al : Ah) + (size_t)(bm0 + row) * Kp + koff + ch * 8;
            cp16(base + half * ABH + SWZ(row * 64 + ch * 16), src);
        }
#pragma unroll
        for (int t = 0; t < BN / 32; t++) {
            int i = tid + t * 256;
            int half = i / (BN * 4);
            int rem = i % (BN * 4);
            int row = rem >> 2, ch = rem & 3;
            const __nv_bfloat16* src =
                (half ? Bl : Bh) + (size_t)(bn0 + row) * Kp + koff + ch * 8;
            cp16(base + 2 * ABH + half * BBH + SWZ(row * 64 + ch * 16), src);
        }
    };

    const int a_row = wm * 32 + (lane & 15);
    const int a_chb = lane >> 4;
    const int b_row = wn * WNCOL + ((lane >> 4) & 1) * 8 + (lane & 7);
    const int b_chb = (lane >> 3) & 1;

    load_stage(0, 0);
    cp_commit();

    for (int c = 0; c < NC; c++) {
        if (c + 1 < NC) {
            load_stage(c + 1, (c + 1) & 1);
            cp_commit();
            cp_wait<1>();
        } else {
            cp_wait<0>();
        }
        __syncthreads();

        const uint32_t base = sb + (c & 1) * STAGE;
        const uint32_t aH = base, aL = base + ABH;
        const uint32_t bH = base + 2 * ABH, bL = bH + BBH;

#pragma unroll
        for (int ks = 0; ks < 2; ks++) {
            uint32_t ah[2][4], al[2][4];
#pragma unroll
            for (int mf = 0; mf < 2; mf++) {
                uint32_t off = SWZ((a_row + mf * 16) * 64 + (ks * 2 + a_chb) * 16);
                ldsm4(ah[mf], aH + off);
                ldsm4(al[mf], aL + off);
            }
            uint32_t bh[NPAIR][4], bl[NPAIR][4];
#pragma unroll
            for (int p = 0; p < NPAIR; p++) {
                uint32_t off = SWZ((b_row + p * 16) * 64 + (ks * 2 + b_chb) * 16);
                ldsm4(bh[p], bH + off);
                ldsm4(bl[p], bL + off);
            }
#pragma unroll
            for (int mf = 0; mf < 2; mf++)
#pragma unroll
                for (int p = 0; p < NPAIR; p++) {
                    mma16816(acc[mf][2 * p],     ah[mf], bh[p][0], bh[p][1]);
                    mma16816(acc[mf][2 * p],     ah[mf], bl[p][0], bl[p][1]);
                    mma16816(acc[mf][2 * p],     al[mf], bh[p][0], bh[p][1]);
                    mma16816(acc[mf][2 * p + 1], ah[mf], bh[p][2], bh[p][3]);
                    mma16816(acc[mf][2 * p + 1], ah[mf], bl[p][2], bl[p][3]);
                    mma16816(acc[mf][2 * p + 1], al[mf], bh[p][2], bh[p][3]);
                }
        }
        __syncthreads();
    }

#pragma unroll
    for (int mf = 0; mf < 2; mf++) {
        int r0 = bm0 + wm * 32 + mf * 16 + (lane >> 2);
#pragma unroll
        for (int nf = 0; nf < NFRAG; nf++) {
            int col = bn0 + wn * WNCOL + nf * 8 + (lane & 3) * 2;
            if (r0 < M)
                *(float2*)(C + (size_t)r0 * N + col) =
                    make_float2(acc[mf][nf][0], acc[mf][nf][1]);
            if (r0 + 8 < M)
                *(float2*)(C + (size_t)(r0 + 8) * N + col) =
                    make_float2(acc[mf][nf][2], acc[mf][nf][3]);
        }
    }
}

// ===========================================================================
// node_prep: per node, es/ed logits, self-loop weight w, acc = w*h, den = w.
// ===========================================================================
__global__ void node_prep4(const float* __restrict__ h,
                           const float* __restrict__ a_src,
                           const float* __restrict__ a_dst,
                           float* __restrict__ es, float* __restrict__ ed,
                           float* __restrict__ acc, float* __restrict__ den, int n) {
    int w = (blockIdx.x * blockDim.x + threadIdx.x) >> 5;
    int lane = threadIdx.x & 31;
    if (w >= n) return;
    int c = lane * 8;
    const float* hp = h + (size_t)w * 256 + c;
    float4 v0 = *(const float4*)(hp);
    float4 v1 = *(const float4*)(hp + 4);
    float4 as0 = *(const float4*)(a_src + c);
    float4 as1 = *(const float4*)(a_src + c + 4);
    float4 ad0 = *(const float4*)(a_dst + c);
    float4 ad1 = *(const float4*)(a_dst + c + 4);
    float s = v0.x * as0.x + v0.y * as0.y + v0.z * as0.z + v0.w * as0.w +
              v1.x * as1.x + v1.y * as1.y + v1.z * as1.z + v1.w * as1.w;
    float d = v0.x * ad0.x + v0.y * ad0.y + v0.z * ad0.z + v0.w * ad0.w +
              v1.x * ad1.x + v1.y * ad1.y + v1.z * ad1.z + v1.w * ad1.w;
#pragma unroll
    for (int o = 4; o; o >>= 1) {
        s += __shfl_xor_sync(0xffffffffu, s, o);
        d += __shfl_xor_sync(0xffffffffu, d, o);
    }
    float e = s + d;
    e = e > 0.f ? e : 0.2f * e;
    float wx = __expf(e);
    float* ap = acc + (size_t)w * 256 + c;
    v0.x *= wx; v0.y *= wx; v0.z *= wx; v0.w *= wx;
    v1.x *= wx; v1.y *= wx; v1.z *= wx; v1.w *= wx;
    *(float4*)(ap) = v0;
    *(float4*)(ap + 4) = v1;
    if ((lane & 7) == 0) {
        int head = lane >> 3;
        es[w * 4 + head] = s;
        ed[w * 4 + head] = d;
        den[w * 4 + head] = wx;
    }
}

__global__ void node_prep1(const float* __restrict__ h,
                           const float* __restrict__ a_src,
                           const float* __restrict__ a_dst,
                           float* __restrict__ es, float* __restrict__ ed,
                           float* __restrict__ acc, float* __restrict__ den, int n) {
    int w = (blockIdx.x * blockDim.x + threadIdx.x) >> 5;
    int lane = threadIdx.x & 31;
    if (w >= n) return;
    int c = lane * 2;
    float2 v = *(const float2*)(h + (size_t)w * 64 + c);
    float2 as = *(const float2*)(a_src + c);
    float2 ad = *(const float2*)(a_dst + c);
    float s = v.x * as.x + v.y * as.y;
    float d = v.x * ad.x + v.y * ad.y;
#pragma unroll
    for (int o = 16; o; o >>= 1) {
        s += __shfl_xor_sync(0xffffffffu, s, o);
        d += __shfl_xor_sync(0xffffffffu, d, o);
    }
    float e = s + d;
    e = e > 0.f ? e : 0.2f * e;
    float wx = __expf(e);
    *(float2*)(acc + (size_t)w * 64 + c) = make_float2(v.x * wx, v.y * wx);
    if (lane == 0) { es[w] = s; ed[w] = d; den[w] = wx; }
}

// ===========================================================================
// agg_fused4: per real edge (1 warp), all lanes compute the 4 head weights
// from broadcast loads (no shuffles), scatter w*h[src] and w into dst.
// ===========================================================================
__global__ void agg_fused4(const int* __restrict__ src, const int* __restrict__ dst,
                           int E_, const float* __restrict__ es,
                           const float* __restrict__ ed,
                           const float* __restrict__ h,
                           float* __restrict__ acc, float* __restrict__ den) {
    int w = (blockIdx.x * blockDim.x + threadIdx.x) >> 5;
    int lane = threadIdx.x & 31;
    if (w >= E_) return;
    int s = src[w], d = dst[w];
    float4 a = *(const float4*)(es + s * 4);   // warp-uniform broadcast
    float4 b = *(const float4*)(ed + d * 4);
    float4 w4; float e;
    e = a.x + b.x; e = e > 0.f ? e : 0.2f * e; w4.x = __expf(e);
    e = a.y + b.y; e = e > 0.f ? e : 0.2f * e; w4.y = __expf(e);
    e = a.z + b.z; e = e > 0.f ? e : 0.2f * e; w4.z = __expf(e);
    e = a.w + b.w; e = e > 0.f ? e : 0.2f * e; w4.w = __expf(e);

    const float* hp = h + (size_t)s * 256;
    float* ap = acc + (size_t)d * 256;
    const int c0 = lane * 4;
    const float alpha0 = (lane < 16) ? w4.x : w4.y;   // heads 0/1
    const float alpha1 = (lane < 16) ? w4.z : w4.w;   // heads 2/3
    {
        float4 v = *(const float4*)(hp + c0);
        v.x *= alpha0; v.y *= alpha0; v.z *= alpha0; v.w *= alpha0;
        red_add_v4(ap + c0, v);
    }
    {
        float4 v = *(const float4*)(hp + c0 + 128);
        v.x *= alpha1; v.y *= alpha1; v.z *= alpha1; v.w *= alpha1;
        red_add_v4(ap + c0 + 128, v);
    }
    if (lane == 0) red_add_v4(den + d * 4, w4);
}

// agg_fused1: half-warp (16 lanes) per edge, 64 feats.
__global__ void agg_fused1(const int* __restrict__ src, const int* __restrict__ dst,
                           int E_, const float* __restrict__ es,
                           const float* __restrict__ ed,
                           const float* __restrict__ h,
                           float* __restrict__ acc, float* __restrict__ den) {
    int t = blockIdx.x * blockDim.x + threadIdx.x;
    int e = t >> 4;
    int sub = t & 15;
    if (e >= E_) return;
    int s = src[e], d = dst[e];
    float x = es[s] + ed[d];
    x = x > 0.f ? x : 0.2f * x;
    float wv = __expf(x);
    int c = sub * 4;
    float4 v = *(const float4*)(h + (size_t)s * 64 + c);
    v.x *= wv; v.y *= wv; v.z *= wv; v.w *= wv;
    red_add_v4(acc + (size_t)d * 64 + c, v);
    if (sub == 0) atomicAdd(den + d, wv);
}

// ===========================================================================
// normalize + bias + ELU + hi/lo split (K fixed 256)
// ===========================================================================
__global__ void conv_split_be(const float* __restrict__ X, const float* __restrict__ den,
                              const float* __restrict__ b,
                              __nv_bfloat16* __restrict__ Hh,
                              __nv_bfloat16* __restrict__ Hl, int M, int Mp) {
    int idx = blockIdx.x * blockDim.x + threadIdx.x;
    if (idx >= Mp * 64) return;
    int row = idx >> 6, q = idx & 63;
    float4 v = make_float4(0.f, 0.f, 0.f, 0.f);
    if (row < M) {
        v = *(const float4*)(X + (size_t)row * 256 + q * 4);
        float dn = den[row * 4 + (q >> 4)];
        float inv = __fdividef(1.f, dn);
        float4 bb = *(const float4*)(b + q * 4);
        v.x = v.x * inv + bb.x; v.y = v.y * inv + bb.y;
        v.z = v.z * inv + bb.z; v.w = v.w * inv + bb.w;
        v.x = v.x > 0.f ? v.x : expm1f(v.x);
        v.y = v.y > 0.f ? v.y : expm1f(v.y);
        v.z = v.z > 0.f ? v.z : expm1f(v.z);
        v.w = v.w > 0.f ? v.w : expm1f(v.w);
    }
    float f[4] = {v.x, v.y, v.z, v.w};
    __nv_bfloat16 h[4], l[4];
#pragma unroll
    for (int j = 0; j < 4; j++) {
        h[j] = __float2bfloat16_rn(f[j]);
        l[j] = __float2bfloat16_rn(f[j] - __bfloat162float(h[j]));
    }
    size_t o = (size_t)row * 256 + q * 4;
    *(__nv_bfloat162*)(Hh + o)     = __nv_bfloat162(h[0], h[1]);
    *(__nv_bfloat162*)(Hh + o + 2) = __nv_bfloat162(h[2], h[3]);
    *(__nv_bfloat162*)(Hl + o)     = __nv_bfloat162(l[0], l[1]);
    *(__nv_bfloat162*)(Hl + o + 2) = __nv_bfloat162(l[2], l[3]);
}

// W [K,N] fp32 -> hi/lo bf16 [N,Kp]
__global__ void conv_wT(const float* __restrict__ W,
                        __nv_bfloat16* __restrict__ Bh,
                        __nv_bfloat16* __restrict__ Bl,
                        int K, int N, int Kp) {
    int idx = blockIdx.x * blockDim.x + threadIdx.x;
    if (idx >= N * Kp) return;
    int n = idx / Kp, k = idx - n * Kp;
    float v = (k < K) ? W[(size_t)k * N + n] : 0.f;
    __nv_bfloat16 h = __float2bfloat16_rn(v);
    __nv_bfloat16 l = __float2bfloat16_rn(v - __bfloat162float(h));
    Bh[(size_t)n * Kp + k] = h;
    Bl[(size_t)n * Kp + k] = l;
}

// ===========================================================================
// final: v = elu(acc/den + b3); out = v @ Wc + bc
// ===========================================================================
__global__ void final_cls(const float* __restrict__ acc, const float* __restrict__ den,
                          const float* __restrict__ b3,
                          const float* __restrict__ Wc, const float* __restrict__ bc,
                          float* __restrict__ out, int n) {
    int w = (blockIdx.x * blockDim.x + threadIdx.x) >> 5;
    int lane = threadIdx.x & 31;
    if (w >= n) return;
    float inv = __fdividef(1.f, den[w]);
    float v0 = acc[(size_t)w * 64 + lane] * inv + b3[lane];
    v0 = v0 > 0.f ? v0 : expm1f(v0);
    float v1 = acc[(size_t)w * 64 + lane + 32] * inv + b3[lane + 32];
    v1 = v1 > 0.f ? v1 : expm1f(v1);
#pragma unroll
    for (int j = 0; j < 3; j++) {
        float p = v0 * Wc[lane * 3 + j] + v1 * Wc[(lane + 32) * 3 + j];
#pragma unroll
        for (int o = 16; o; o >>= 1) p += __shfl_xor_sync(0xffffffffu, p, o);
        if (lane == 0) out[w * 3 + j] = p + bc[j];
    }
}

// ===========================================================================
static inline int cdiv(int a, int b) { return (a + b - 1) / b; }

extern "C" void kernel_launch(void* const* d_in, const int* in_sizes, int n_in,
                              void* d_out, int out_size) {
    const float* x    = (const float*)d_in[0];
    const float* W1   = (const float*)d_in[1];
    const float* a1s  = (const float*)d_in[2];
    const float* a1d  = (const float*)d_in[3];
    const float* b1   = (const float*)d_in[4];
    const float* W2   = (const float*)d_in[5];
    const float* a2s  = (const float*)d_in[6];
    const float* a2d  = (const float*)d_in[7];
    const float* b2   = (const float*)d_in[8];
    const float* W3   = (const float*)d_in[9];
    const float* a3s  = (const float*)d_in[10];
    const float* a3d  = (const float*)d_in[11];
    const float* b3   = (const float*)d_in[12];
    const float* Wc   = (const float*)d_in[13];
    const float* bc   = (const float*)d_in[14];
    const int*   ei   = (const int*)d_in[15];
    float* out = (float*)d_out;

    const int N = GAT_N, E = GAT_E, Mp = GAT_Mp;
    const int* src = ei;
    const int* dst = ei + E;

    float *hA, *hB, *h3, *acc3, *es, *ed, *den;
    __nv_bfloat16 *Ahp, *Alp, *Bhp, *Blp;
    cudaGetSymbolAddress((void**)&hA,   g_hA);
    cudaGetSymbolAddress((void**)&hB,   g_hB);
    cudaGetSymbolAddress((void**)&h3,   g_h3);
    cudaGetSymbolAddress((void**)&acc3, g_acc3);
    cudaGetSymbolAddress((void**)&es,   g_es);
    cudaGetSymbolAddress((void**)&ed,   g_ed);
    cudaGetSymbolAddress((void**)&den,  g_den);
    cudaGetSymbolAddress((void**)&Ahp,  g_Ah);
    cudaGetSymbolAddress((void**)&Alp,  g_Al);
    cudaGetSymbolAddress((void**)&Bhp,  g_Bh);
    cudaGetSymbolAddress((void**)&Blp,  g_Bl);

    const int SMF   = 2 * 32768;
    const int SM128 = 2 * (2 * 8192 + 2 * 128 * 64);
    const int SM64  = 2 * (2 * 8192 + 2 * 64 * 64);
    cudaFuncSetAttribute(gemm_fused,    cudaFuncAttributeMaxDynamicSharedMemorySize, SMF);
    cudaFuncSetAttribute(gemm_mma<128>, cudaFuncAttributeMaxDynamicSharedMemorySize, SM128);
    cudaFuncSetAttribute(gemm_mma<64>,  cudaFuncAttributeMaxDynamicSharedMemorySize, SM64);

    const int TB = 256;
    const int MT = Mp / 128;              // 235
    const int NPB = cdiv(N * 32, TB);     // node_prep / final blocks
    const int AGB = cdiv(E * 32, TB);     // agg4 blocks (warp/edge)
    const int AGB1 = cdiv(E * 16, TB);    // agg1 blocks (half-warp/edge)

    // ---------------- layer 1 (H=4, K=5000) ----------------
    conv_wT<<<cdiv(256 * GAT_K1P, TB), TB>>>(W1, Bhp, Blp, GAT_DIN, 256, GAT_K1P);
    gemm_fused<<<dim3(2, MT), 256, SMF>>>(x, Bhp, Blp, hA, N, GAT_DIN, GAT_K1P);
    node_prep4<<<NPB, TB>>>(hA, a1s, a1d, es, ed, hB, den, N);
    agg_fused4<<<AGB, TB>>>(src, dst, E, es, ed, hA, hB, den);

    // ---------------- layer 2 (H=4, K=256) ----------------
    conv_split_be<<<cdiv(Mp * 64, TB), TB>>>(hB, den, b1, Ahp, Alp, N, Mp);
    conv_wT<<<cdiv(256 * 256, TB), TB>>>(W2, Bhp, Blp, 256, 256, 256);
    gemm_mma<128><<<dim3(2, MT), 256, SM128>>>(Ahp, Alp, Bhp, Blp, hA, N, 256, 256);
    node_prep4<<<NPB, TB>>>(hA, a2s, a2d, es, ed, hB, den, N);
    agg_fused4<<<AGB, TB>>>(src, dst, E, es, ed, hA, hB, den);

    // ---------------- layer 3 (H=1, K=256, N=64) ----------------
    conv_split_be<<<cdiv(Mp * 64, TB), TB>>>(hB, den, b2, Ahp, Alp, N, Mp);
    conv_wT<<<cdiv(64 * 256, TB), TB>>>(W3, Bhp, Blp, 256, 64, 256);
    gemm_mma<64><<<dim3(1, MT), 256, SM64>>>(Ahp, Alp, Bhp, Blp, h3, N, 64, 256);
    node_prep1<<<NPB, TB>>>(h3, a3s, a3d, es, ed, acc3, den, N);
    agg_fused1<<<AGB1, TB>>>(src, dst, E, es, ed, h3, acc3, den);
    final_cls<<<NPB, TB>>>(acc3, den, b3, Wc, bc, out, N);
}

// round 7
// speedup vs baseline: 1.1638x; 1.1257x over previous
#include <cuda_runtime.h>
#include <cuda_bf16.h>
#include <cstdint>

// ---------------------------------------------------------------------------
// SentimentGAT on GB300 (sm_103 baseline PTX): bf16x3 mma.sync GEMMs +
// CSR-gather attention (no scatter atomics), fused normalize/bias/ELU/split.
// ---------------------------------------------------------------------------

#define GAT_N   30000
#define GAT_Mp  30080               // 235 * 128
#define GAT_E   480000
#define GAT_DIN 5000
#define GAT_K1P 5056                // 79 * 64 (padded K stride for W1^T)

// ---- fp32 scratch ----
__device__ float g_hA[GAT_N * 256];
__device__ float g_h3[GAT_N * 64];
__device__ float g_es[GAT_N * 4];
__device__ float g_ed[GAT_N * 4];

// ---- CSR ----
__device__ int g_rowoff[GAT_N + 1];
__device__ int g_cursor[GAT_N];
__device__ int g_csrsrc[GAT_E];

// ---- bf16 hi/lo scratch ----
__device__ __align__(128) __nv_bfloat16 g_Ah[(size_t)GAT_Mp * 256];
__device__ __align__(128) __nv_bfloat16 g_Al[(size_t)GAT_Mp * 256];
__device__ __align__(128) __nv_bfloat16 g_Bh[256 * GAT_K1P];
__device__ __align__(128) __nv_bfloat16 g_Bl[256 * GAT_K1P];

// ===========================================================================
// low-level helpers
// ===========================================================================
#define SWZ(o) ((o) ^ (((o) >> 3) & 0x70))

__device__ __forceinline__ uint32_t smem_u32(const void* p) {
    uint32_t a;
    asm("{ .reg .u64 t; cvta.to.shared.u64 t, %1; cvt.u32.u64 %0, t; }"
        : "=r"(a) : "l"(p));
    return a;
}
__device__ __forceinline__ void cp16(uint32_t d, const void* s) {
    asm volatile("cp.async.cg.shared.global [%0], [%1], 16;" :: "r"(d), "l"(s));
}
__device__ __forceinline__ void cp16z(uint32_t d, const void* s, bool pred) {
    int sz = pred ? 16 : 0;
    asm volatile("cp.async.cg.shared.global [%0], [%1], 16, %2;"
                 :: "r"(d), "l"(s), "r"(sz));
}
__device__ __forceinline__ void cp_commit() {
    asm volatile("cp.async.commit_group;" ::: "memory");
}
template <int Ng>
__device__ __forceinline__ void cp_wait() {
    asm volatile("cp.async.wait_group %0;" :: "n"(Ng) : "memory");
}
__device__ __forceinline__ void ldsm4(uint32_t (&r)[4], uint32_t addr) {
    asm volatile("ldmatrix.sync.aligned.m8n8.x4.shared.b16 {%0,%1,%2,%3}, [%4];"
                 : "=r"(r[0]), "=r"(r[1]), "=r"(r[2]), "=r"(r[3]) : "r"(addr));
}
__device__ __forceinline__ void mma16816(float (&d)[4], const uint32_t (&a)[4],
                                         uint32_t b0, uint32_t b1) {
    asm volatile("mma.sync.aligned.m16n8k16.row.col.f32.bf16.bf16.f32 "
                 "{%0,%1,%2,%3}, {%4,%5,%6,%7}, {%8,%9}, {%0,%1,%2,%3};"
                 : "+f"(d[0]), "+f"(d[1]), "+f"(d[2]), "+f"(d[3])
                 : "r"(a[0]), "r"(a[1]), "r"(a[2]), "r"(a[3]), "r"(b0), "r"(b1));
}
__device__ __forceinline__ uint32_t bfpack(float a, float b) {
    return (uint32_t)__bfloat16_as_ushort(__float2bfloat16_rn(a)) |
           ((uint32_t)__bfloat16_as_ushort(__float2bfloat16_rn(b)) << 16);
}
__device__ __forceinline__ float sel4(float4 v, int i) {
    float a = (i & 1) ? v.y : v.x;
    float b = (i & 1) ? v.w : v.z;
    return (i & 2) ? b : a;
}

// ===========================================================================
// CSR build
// ===========================================================================
__global__ void csr_zero(int* cur, int n) {
    int i = blockIdx.x * blockDim.x + threadIdx.x;
    if (i < n) cur[i] = 0;
}
__global__ void csr_hist(const int* __restrict__ dst, int* cur, int E_) {
    int i = blockIdx.x * blockDim.x + threadIdx.x;
    if (i < E_) atomicAdd(&cur[dst[i]], 1);
}
__global__ void csr_scan(int* degcur, int* rowoff, int n) {
    __shared__ int sh[1024];
    __shared__ int carry_s;
    int tid = threadIdx.x;
    if (tid == 0) carry_s = 0;
    __syncthreads();
    for (int base = 0; base < n; base += 1024) {
        int i = base + tid;
        int v = (i < n) ? degcur[i] : 0;
        sh[tid] = v;
        __syncthreads();
#pragma unroll
        for (int o = 1; o < 1024; o <<= 1) {
            int t = (tid >= o) ? sh[tid - o] : 0;
            __syncthreads();
            sh[tid] += t;
            __syncthreads();
        }
        int excl = sh[tid] - v + carry_s;
        if (i < n) { rowoff[i] = excl; degcur[i] = excl; }
        __syncthreads();
        if (tid == 1023) carry_s += sh[1023];
        __syncthreads();
    }
    if (tid == 0) rowoff[n] = carry_s;
}
__global__ void csr_fill(const int* __restrict__ src, const int* __restrict__ dst,
                         int* cur, int* csrsrc, int E_) {
    int i = blockIdx.x * blockDim.x + threadIdx.x;
    if (i < E_) {
        int p = atomicAdd(&cur[dst[i]], 1);
        csrsrc[p] = src[i];
    }
}

// ===========================================================================
// FUSED layer-1 GEMM (R4-proven body): C[M,256] = split3(X) @ split3(W1)^T
// blockIdx.x = N-half (schedule-adjacent -> X dedup in L2), blockIdx.y = M tile
// ===========================================================================
__global__ __launch_bounds__(256)
void gemm_fused(const float* __restrict__ X,
                const __nv_bfloat16* __restrict__ Bh, const __nv_bfloat16* __restrict__ Bl,
                float* __restrict__ C, int M, int K, int KpB) {
    constexpr int STAGE = 49152;
    extern __shared__ char smem[];
    const uint32_t sb = smem_u32(smem);

    const int tid = threadIdx.x;
    const int wid = tid >> 5, lane = tid & 31;
    const int wm = wid & 3, wn = wid >> 2;
    const int bm0 = blockIdx.y * 128;
    const int bn0 = blockIdx.x * 128;

    float acc[2][8][4];
#pragma unroll
    for (int i = 0; i < 2; i++)
#pragma unroll
        for (int j = 0; j < 8; j++)
#pragma unroll
            for (int k = 0; k < 4; k++) acc[i][j][k] = 0.f;

    const int NC = (K + 31) >> 5;

    auto load_stage = [&](int c, int stg) {
        const uint32_t base = sb + stg * STAGE;
        const int k0 = c * 32;
#pragma unroll
        for (int t = 0; t < 4; t++) {
            int i = tid + t * 256;
            int row = i >> 3, q = i & 7;
            int gm = bm0 + row, gk = k0 + q * 4;
            bool p = (gm < M) && (gk < K);
            cp16z(base + row * 128 + q * 16, X + (p ? ((size_t)gm * K + gk) : 0), p);
        }
#pragma unroll
        for (int t = 0; t < 4; t++) {
            int i = tid + t * 256;
            int half = i >> 9;
            int rem = i & 511;
            int row = rem >> 2, ch = rem & 3;
            const __nv_bfloat16* src =
                (half ? Bl : Bh) + (size_t)(bn0 + row) * KpB + k0 + ch * 8;
            cp16(base + 32768 + half * 8192 + SWZ(row * 64 + ch * 16), src);
        }
    };

    const int a_row = wm * 32 + (lane & 15);
    const int a_chb = lane >> 4;
    const int b_row = wn * 64 + ((lane >> 4) & 1) * 8 + (lane & 7);
    const int b_chb = (lane >> 3) & 1;

    load_stage(0, 0);
    cp_commit();

    for (int c = 0; c < NC; c++) {
        const int stg = c & 1;
        const uint32_t base = sb + stg * STAGE;
        cp_wait<0>();
        __syncthreads();
#pragma unroll
        for (int t = 0; t < 2; t++) {
            int i = tid + t * 256;
            int row = i >> 2, ch = i & 3;
            const float4* fp = (const float4*)(smem + stg * STAGE + row * 128 + ch * 32);
            float4 v0 = fp[0], v1 = fp[1];
            float f[8] = {v0.x, v0.y, v0.z, v0.w, v1.x, v1.y, v1.z, v1.w};
            uint32_t hi[4], lo[4];
#pragma unroll
            for (int k = 0; k < 4; k++) {
                float h0 = __bfloat162float(__float2bfloat16_rn(f[2 * k]));
                float h1 = __bfloat162float(__float2bfloat16_rn(f[2 * k + 1]));
                hi[k] = bfpack(f[2 * k], f[2 * k + 1]);
                lo[k] = bfpack(f[2 * k] - h0, f[2 * k + 1] - h1);
            }
            uint32_t off = SWZ(row * 64 + ch * 16);
            *(uint4*)(smem + stg * STAGE + 16384 + off) = make_uint4(hi[0], hi[1], hi[2], hi[3]);
            *(uint4*)(smem + stg * STAGE + 24576 + off) = make_uint4(lo[0], lo[1], lo[2], lo[3]);
        }
        __syncthreads();
        if (c + 1 < NC) {
            load_stage(c + 1, stg ^ 1);
            cp_commit();
        }

        const uint32_t aH = base + 16384, aL = base + 24576;
        const uint32_t bH = base + 32768, bL = base + 40960;
#pragma unroll
        for (int ks = 0; ks < 2; ks++) {
            uint32_t ah[2][4], al[2][4];
#pragma unroll
            for (int mf = 0; mf < 2; mf++) {
                uint32_t off = SWZ((a_row + mf * 16) * 64 + (ks * 2 + a_chb) * 16);
                ldsm4(ah[mf], aH + off);
                ldsm4(al[mf], aL + off);
            }
            uint32_t bh[4][4], bl[4][4];
#pragma unroll
            for (int p = 0; p < 4; p++) {
                uint32_t off = SWZ((b_row + p * 16) * 64 + (ks * 2 + b_chb) * 16);
                ldsm4(bh[p], bH + off);
                ldsm4(bl[p], bL + off);
            }
#pragma unroll
            for (int mf = 0; mf < 2; mf++)
#pragma unroll
                for (int p = 0; p < 4; p++) {
                    mma16816(acc[mf][2 * p],     ah[mf], bh[p][0], bh[p][1]);
                    mma16816(acc[mf][2 * p],     ah[mf], bl[p][0], bl[p][1]);
                    mma16816(acc[mf][2 * p],     al[mf], bh[p][0], bh[p][1]);
                    mma16816(acc[mf][2 * p + 1], ah[mf], bh[p][2], bh[p][3]);
                    mma16816(acc[mf][2 * p + 1], ah[mf], bl[p][2], bl[p][3]);
                    mma16816(acc[mf][2 * p + 1], al[mf], bh[p][2], bh[p][3]);
                }
        }
    }

#pragma unroll
    for (int mf = 0; mf < 2; mf++) {
        int r0 = bm0 + wm * 32 + mf * 16 + (lane >> 2);
#pragma unroll
        for (int nf = 0; nf < 8; nf++) {
            int col = bn0 + wn * 64 + nf * 8 + (lane & 3) * 2;
            if (r0 < M)
                *(float2*)(C + (size_t)r0 * 256 + col) =
                    make_float2(acc[mf][nf][0], acc[mf][nf][1]);
            if (r0 + 8 < M)
                *(float2*)(C + (size_t)(r0 + 8) * 256 + col) =
                    make_float2(acc[mf][nf][2], acc[mf][nf][3]);
        }
    }
}

// ===========================================================================
// pre-split GEMM for layers 2/3 (proven)
// ===========================================================================
template <int BN>
__global__ __launch_bounds__(256)
void gemm_mma(const __nv_bfloat16* __restrict__ Ah, const __nv_bfloat16* __restrict__ Al,
              const __nv_bfloat16* __restrict__ Bh, const __nv_bfloat16* __restrict__ Bl,
              float* __restrict__ C, int M, int N, int Kp) {
    constexpr int WNCOL = BN / 2;
    constexpr int NFRAG = WNCOL / 8;
    constexpr int NPAIR = NFRAG / 2;
    constexpr int ABH = 8192;
    constexpr int BBH = BN * 64;
    constexpr int STAGE = 2 * ABH + 2 * BBH;

    extern __shared__ char smem[];
    const uint32_t sb = smem_u32(smem);

    const int tid = threadIdx.x;
    const int wid = tid >> 5, lane = tid & 31;
    const int wm = wid & 3, wn = wid >> 2;
    const int bm0 = blockIdx.y * 128;
    const int bn0 = blockIdx.x * BN;

    float acc[2][NFRAG][4];
#pragma unroll
    for (int i = 0; i < 2; i++)
#pragma unroll
        for (int j = 0; j < NFRAG; j++)
#pragma unroll
            for (int k = 0; k < 4; k++) acc[i][j][k] = 0.f;

    const int NC = Kp >> 5;

    auto load_stage = [&](int c, int stg) {
        const uint32_t base = sb + stg * STAGE;
        const size_t koff = (size_t)c * 32;
#pragma unroll
        for (int t = 0; t < 4; t++) {
            int i = tid + t * 256;
            int half = i >> 9;
            int rem = i & 511;
            int row = rem >> 2, ch = rem & 3;
            const __nv_bfloat16* src =
                (half ? Al : Ah) + (size_t)(bm0 + row) * Kp + koff + ch * 8;
            cp16(base + half * ABH + SWZ(row * 64 + ch * 16), src);
        }
#pragma unroll
        for (int t = 0; t < BN / 32; t++) {
            int i = tid + t * 256;
            int half = i / (BN * 4);
            int rem = i % (BN * 4);
            int row = rem >> 2, ch = rem & 3;
            const __nv_bfloat16* src =
                (half ? Bl : Bh) + (size_t)(bn0 + row) * Kp + koff + ch * 8;
            cp16(base + 2 * ABH + half * BBH + SWZ(row * 64 + ch * 16), src);
        }
    };

    const int a_row = wm * 32 + (lane & 15);
    const int a_chb = lane >> 4;
    const int b_row = wn * WNCOL + ((lane >> 4) & 1) * 8 + (lane & 7);
    const int b_chb = (lane >> 3) & 1;

    load_stage(0, 0);
    cp_commit();

    for (int c = 0; c < NC; c++) {
        if (c + 1 < NC) {
            load_stage(c + 1, (c + 1) & 1);
            cp_commit();
            cp_wait<1>();
        } else {
            cp_wait<0>();
        }
        __syncthreads();

        const uint32_t base = sb + (c & 1) * STAGE;
        const uint32_t aH = base, aL = base + ABH;
        const uint32_t bH = base + 2 * ABH, bL = bH + BBH;

#pragma unroll
        for (int ks = 0; ks < 2; ks++) {
            uint32_t ah[2][4], al[2][4];
#pragma unroll
            for (int mf = 0; mf < 2; mf++) {
                uint32_t off = SWZ((a_row + mf * 16) * 64 + (ks * 2 + a_chb) * 16);
                ldsm4(ah[mf], aH + off);
                ldsm4(al[mf], aL + off);
            }
            uint32_t bh[NPAIR][4], bl[NPAIR][4];
#pragma unroll
            for (int p = 0; p < NPAIR; p++) {
                uint32_t off = SWZ((b_row + p * 16) * 64 + (ks * 2 + b_chb) * 16);
                ldsm4(bh[p], bH + off);
                ldsm4(bl[p], bL + off);
            }
#pragma unroll
            for (int mf = 0; mf < 2; mf++)
#pragma unroll
                for (int p = 0; p < NPAIR; p++) {
                    mma16816(acc[mf][2 * p],     ah[mf], bh[p][0], bh[p][1]);
                    mma16816(acc[mf][2 * p],     ah[mf], bl[p][0], bl[p][1]);
                    mma16816(acc[mf][2 * p],     al[mf], bh[p][0], bh[p][1]);
                    mma16816(acc[mf][2 * p + 1], ah[mf], bh[p][2], bh[p][3]);
                    mma16816(acc[mf][2 * p + 1], ah[mf], bl[p][2], bl[p][3]);
                    mma16816(acc[mf][2 * p + 1], al[mf], bh[p][2], bh[p][3]);
                }
        }
        __syncthreads();
    }

#pragma unroll
    for (int mf = 0; mf < 2; mf++) {
        int r0 = bm0 + wm * 32 + mf * 16 + (lane >> 2);
#pragma unroll
        for (int nf = 0; nf < NFRAG; nf++) {
            int col = bn0 + wn * WNCOL + nf * 8 + (lane & 3) * 2;
            if (r0 < M)
                *(float2*)(C + (size_t)r0 * N + col) =
                    make_float2(acc[mf][nf][0], acc[mf][nf][1]);
            if (r0 + 8 < M)
                *(float2*)(C + (size_t)(r0 + 8) * N + col) =
                    make_float2(acc[mf][nf][2], acc[mf][nf][3]);
        }
    }
}

// ===========================================================================
// es/ed logits only (one warp per node)
// ===========================================================================
__global__ void es_ed4(const float* __restrict__ h,
                       const float* __restrict__ a_src,
                       const float* __restrict__ a_dst,
                       float* __restrict__ es, float* __restrict__ ed, int n) {
    int w = (blockIdx.x * blockDim.x + threadIdx.x) >> 5;
    int lane = threadIdx.x & 31;
    if (w >= n) return;
    int c = lane * 8;
    const float* hp = h + (size_t)w * 256 + c;
    float4 v0 = *(const float4*)(hp);
    float4 v1 = *(const float4*)(hp + 4);
    float4 as0 = *(const float4*)(a_src + c);
    float4 as1 = *(const float4*)(a_src + c + 4);
    float4 ad0 = *(const float4*)(a_dst + c);
    float4 ad1 = *(const float4*)(a_dst + c + 4);
    float s = v0.x * as0.x + v0.y * as0.y + v0.z * as0.z + v0.w * as0.w +
              v1.x * as1.x + v1.y * as1.y + v1.z * as1.z + v1.w * as1.w;
    float d = v0.x * ad0.x + v0.y * ad0.y + v0.z * ad0.z + v0.w * ad0.w +
              v1.x * ad1.x + v1.y * ad1.y + v1.z * ad1.z + v1.w * ad1.w;
#pragma unroll
    for (int o = 4; o; o >>= 1) {
        s += __shfl_xor_sync(0xffffffffu, s, o);
        d += __shfl_xor_sync(0xffffffffu, d, o);
    }
    if ((lane & 7) == 0) {
        int head = lane >> 3;
        es[w * 4 + head] = s;
        ed[w * 4 + head] = d;
    }
}

__global__ void es_ed1(const float* __restrict__ h,
                       const float* __restrict__ a_src,
                       const float* __restrict__ a_dst,
                       float* __restrict__ es, float* __restrict__ ed, int n) {
    int w = (blockIdx.x * blockDim.x + threadIdx.x) >> 5;
    int lane = threadIdx.x & 31;
    if (w >= n) return;
    int c = lane * 2;
    float2 v = *(const float2*)(h + (size_t)w * 64 + c);
    float2 as = *(const float2*)(a_src + c);
    float2 ad = *(const float2*)(a_dst + c);
    float s = v.x * as.x + v.y * as.y;
    float d = v.x * ad.x + v.y * ad.y;
#pragma unroll
    for (int o = 16; o; o >>= 1) {
        s += __shfl_xor_sync(0xffffffffu, s, o);
        d += __shfl_xor_sync(0xffffffffu, d, o);
    }
    if (lane == 0) { es[w] = s; ed[w] = d; }
}

// ===========================================================================
// agg_gather4: one warp per dst node. Register-accumulate self + in-edges,
// normalize, +bias, ELU, bf16 hi/lo split -> next GEMM A operand.
// Rows n..Mp zero-padded.
// ===========================================================================
__global__ void agg_gather4(const int* __restrict__ rowoff, const int* __restrict__ csrsrc,
                            const float* __restrict__ es, const float* __restrict__ ed,
                            const float* __restrict__ h, const float* __restrict__ b,
                            __nv_bfloat16* __restrict__ Hh, __nv_bfloat16* __restrict__ Hl,
                            int n, int Mp) {
    int w = (blockIdx.x * blockDim.x + threadIdx.x) >> 5;
    int lane = threadIdx.x & 31;
    if (w >= Mp) return;
    const int c0 = lane * 4;
    if (w >= n) {   // zero-pad rows
        *(uint2*)(Hh + (size_t)w * 256 + c0) = make_uint2(0, 0);
        *(uint2*)(Hh + (size_t)w * 256 + c0 + 128) = make_uint2(0, 0);
        *(uint2*)(Hl + (size_t)w * 256 + c0) = make_uint2(0, 0);
        *(uint2*)(Hl + (size_t)w * 256 + c0 + 128) = make_uint2(0, 0);
        return;
    }
    const int myh = lane & 3;
    const int hs = (lane >> 4) & 1;                     // head pair select
    float4 ed4 = *(const float4*)(ed + w * 4);          // broadcast
    float edh = sel4(ed4, myh);

    // self loop
    float4 es4 = *(const float4*)(es + w * 4);
    float e = sel4(es4, myh) + edh;
    e = e > 0.f ? e : 0.2f * e;
    float wv = __expf(e);
    float den = wv;
    float al0 = __shfl_sync(0xffffffffu, wv, hs);       // head 0/1
    float al1 = __shfl_sync(0xffffffffu, wv, 2 + hs);   // head 2/3

    const float* hp = h + (size_t)w * 256;
    float4 a0 = *(const float4*)(hp + c0);
    float4 a1 = *(const float4*)(hp + c0 + 128);
    a0.x *= al0; a0.y *= al0; a0.z *= al0; a0.w *= al0;
    a1.x *= al1; a1.y *= al1; a1.z *= al1; a1.w *= al1;

    int j0 = rowoff[w], j1 = rowoff[w + 1];
    int s = (j0 < j1) ? csrsrc[j0] : 0;
    for (int j = j0; j < j1; j++) {
        int snext = (j + 1 < j1) ? csrsrc[j + 1] : 0;
        float4 e4 = *(const float4*)(es + s * 4);       // broadcast
        float ee = sel4(e4, myh) + edh;
        ee = ee > 0.f ? ee : 0.2f * ee;
        float wj = __expf(ee);
        den += wj;
        float b0 = __shfl_sync(0xffffffffu, wj, hs);
        float b1 = __shfl_sync(0xffffffffu, wj, 2 + hs);
        const float* sp = h + (size_t)s * 256;
        float4 v0 = *(const float4*)(sp + c0);
        float4 v1 = *(const float4*)(sp + c0 + 128);
        a0.x += b0 * v0.x; a0.y += b0 * v0.y; a0.z += b0 * v0.z; a0.w += b0 * v0.w;
        a1.x += b1 * v1.x; a1.y += b1 * v1.y; a1.z += b1 * v1.z; a1.w += b1 * v1.w;
        s = snext;
    }
    float inv0 = __fdividef(1.f, __shfl_sync(0xffffffffu, den, hs));
    float inv1 = __fdividef(1.f, __shfl_sync(0xffffffffu, den, 2 + hs));

    float4 bb0 = *(const float4*)(b + c0);
    float4 bb1 = *(const float4*)(b + c0 + 128);
    float f0[4] = {a0.x * inv0 + bb0.x, a0.y * inv0 + bb0.y,
                   a0.z * inv0 + bb0.z, a0.w * inv0 + bb0.w};
    float f1[4] = {a1.x * inv1 + bb1.x, a1.y * inv1 + bb1.y,
                   a1.z * inv1 + bb1.z, a1.w * inv1 + bb1.w};
#pragma unroll
    for (int k = 0; k < 4; k++) {
        f0[k] = f0[k] > 0.f ? f0[k] : expm1f(f0[k]);
        f1[k] = f1[k] > 0.f ? f1[k] : expm1f(f1[k]);
    }
    uint32_t h0a = bfpack(f0[0], f0[1]), h0b = bfpack(f0[2], f0[3]);
    uint32_t h1a = bfpack(f1[0], f1[1]), h1b = bfpack(f1[2], f1[3]);
    float r0[4], r1[4];
#pragma unroll
    for (int k = 0; k < 4; k++) {
        r0[k] = f0[k] - __bfloat162float(__float2bfloat16_rn(f0[k]));
        r1[k] = f1[k] - __bfloat162float(__float2bfloat16_rn(f1[k]));
    }
    size_t o = (size_t)w * 256 + c0;
    *(uint2*)(Hh + o)       = make_uint2(h0a, h0b);
    *(uint2*)(Hh + o + 128) = make_uint2(h1a, h1b);
    *(uint2*)(Hl + o)       = make_uint2(bfpack(r0[0], r0[1]), bfpack(r0[2], r0[3]));
    *(uint2*)(Hl + o + 128) = make_uint2(bfpack(r1[0], r1[1]), bfpack(r1[2], r1[3]));
}

// ===========================================================================
// agg_gather1 + classifier: one warp per node.
// v = elu(agg(h3)/den + b3); out = v @ Wc + bc
// ===========================================================================
__global__ void agg_gather1(const int* __restrict__ rowoff, const int* __restrict__ csrsrc,
                            const float* __restrict__ es, const float* __restrict__ ed,
                            const float* __restrict__ h, const float* __restrict__ b3,
                            const float* __restrict__ Wc, const float* __restrict__ bc,
                            float* __restrict__ out, int n) {
    int w = (blockIdx.x * blockDim.x + threadIdx.x) >> 5;
    int lane = threadIdx.x & 31;
    if (w >= n) return;
    float edw = ed[w];
    float e = es[w] + edw;
    e = e > 0.f ? e : 0.2f * e;
    float wv = __expf(e);
    float den = wv;
    float v0 = h[(size_t)w * 64 + lane] * wv;
    float v1 = h[(size_t)w * 64 + lane + 32] * wv;

    int j0 = rowoff[w], j1 = rowoff[w + 1];
    int s = (j0 < j1) ? csrsrc[j0] : 0;
    for (int j = j0; j < j1; j++) {
        int snext = (j + 1 < j1) ? csrsrc[j + 1] : 0;
        float ee = es[s] + edw;
        ee = ee > 0.f ? ee : 0.2f * ee;
        float wj = __expf(ee);
        den += wj;
        v0 += wj * h[(size_t)s * 64 + lane];
        v1 += wj * h[(size_t)s * 64 + lane + 32];
        s = snext;
    }
    float inv = __fdividef(1.f, den);
    v0 = v0 * inv + b3[lane];
    v0 = v0 > 0.f ? v0 : expm1f(v0);
    v1 = v1 * inv + b3[lane + 32];
    v1 = v1 > 0.f ? v1 : expm1f(v1);
#pragma unroll
    for (int j = 0; j < 3; j++) {
        float p = v0 * Wc[lane * 3 + j] + v1 * Wc[(lane + 32) * 3 + j];
#pragma unroll
        for (int o = 16; o; o >>= 1) p += __shfl_xor_sync(0xffffffffu, p, o);
        if (lane == 0) out[w * 3 + j] = p + bc[j];
    }
}

// ===========================================================================
// W [K,N] fp32 -> hi/lo bf16 [N,Kp]
// ===========================================================================
__global__ void conv_wT(const float* __restrict__ W,
                        __nv_bfloat16* __restrict__ Bh,
                        __nv_bfloat16* __restrict__ Bl,
                        int K, int N, int Kp) {
    int idx = blockIdx.x * blockDim.x + threadIdx.x;
    if (idx >= N * Kp) return;
    int n = idx / Kp, k = idx - n * Kp;
    float v = (k < K) ? W[(size_t)k * N + n] : 0.f;
    __nv_bfloat16 h = __float2bfloat16_rn(v);
    __nv_bfloat16 l = __float2bfloat16_rn(v - __bfloat162float(h));
    Bh[(size_t)n * Kp + k] = h;
    Bl[(size_t)n * Kp + k] = l;
}

// ===========================================================================
static inline int cdiv(int a, int b) { return (a + b - 1) / b; }

extern "C" void kernel_launch(void* const* d_in, const int* in_sizes, int n_in,
                              void* d_out, int out_size) {
    const float* x    = (const float*)d_in[0];
    const float* W1   = (const float*)d_in[1];
    const float* a1s  = (const float*)d_in[2];
    const float* a1d  = (const float*)d_in[3];
    const float* b1   = (const float*)d_in[4];
    const float* W2   = (const float*)d_in[5];
    const float* a2s  = (const float*)d_in[6];
    const float* a2d  = (const float*)d_in[7];
    const float* b2   = (const float*)d_in[8];
    const float* W3   = (const float*)d_in[9];
    const float* a3s  = (const float*)d_in[10];
    const float* a3d  = (const float*)d_in[11];
    const float* b3   = (const float*)d_in[12];
    const float* Wc   = (const float*)d_in[13];
    const float* bc   = (const float*)d_in[14];
    const int*   ei   = (const int*)d_in[15];
    float* out = (float*)d_out;

    const int N = GAT_N, E = GAT_E, Mp = GAT_Mp;
    const int* src = ei;
    const int* dst = ei + E;

    float *hA, *h3, *es, *ed;
    int *rowoff, *cursor, *csrsrc;
    __nv_bfloat16 *Ahp, *Alp, *Bhp, *Blp;
    cudaGetSymbolAddress((void**)&hA,     g_hA);
    cudaGetSymbolAddress((void**)&h3,     g_h3);
    cudaGetSymbolAddress((void**)&es,     g_es);
    cudaGetSymbolAddress((void**)&ed,     g_ed);
    cudaGetSymbolAddress((void**)&rowoff, g_rowoff);
    cudaGetSymbolAddress((void**)&cursor, g_cursor);
    cudaGetSymbolAddress((void**)&csrsrc, g_csrsrc);
    cudaGetSymbolAddress((void**)&Ahp,    g_Ah);
    cudaGetSymbolAddress((void**)&Alp,    g_Al);
    cudaGetSymbolAddress((void**)&Bhp,    g_Bh);
    cudaGetSymbolAddress((void**)&Blp,    g_Bl);

    const int SMF   = 2 * 49152;
    const int SM128 = 2 * (2 * 8192 + 2 * 128 * 64);
    const int SM64  = 2 * (2 * 8192 + 2 * 64 * 64);
    cudaFuncSetAttribute(gemm_fused,    cudaFuncAttributeMaxDynamicSharedMemorySize, SMF);
    cudaFuncSetAttribute(gemm_mma<128>, cudaFuncAttributeMaxDynamicSharedMemorySize, SM128);
    cudaFuncSetAttribute(gemm_mma<64>,  cudaFuncAttributeMaxDynamicSharedMemorySize, SM64);

    const int TB = 256;
    const int MT = Mp / 128;               // 235
    const int NPB = cdiv(N * 32, TB);      // warp-per-node blocks
    const int GPB = cdiv(Mp * 32, TB);     // warp-per-padded-node blocks

    // ---------------- CSR build (graph shared by all 3 layers) ----------------
    csr_zero<<<cdiv(N, TB), TB>>>(cursor, N);
    csr_hist<<<cdiv(E, TB), TB>>>(dst, cursor, E);
    csr_scan<<<1, 1024>>>(cursor, rowoff, N);
    csr_fill<<<cdiv(E, TB), TB>>>(src, dst, cursor, csrsrc, E);

    // ---------------- layer 1 (H=4, K=5000) ----------------
    conv_wT<<<cdiv(256 * GAT_K1P, TB), TB>>>(W1, Bhp, Blp, GAT_DIN, 256, GAT_K1P);
    gemm_fused<<<dim3(2, MT), 256, SMF>>>(x, Bhp, Blp, hA, N, GAT_DIN, GAT_K1P);
    es_ed4<<<NPB, TB>>>(hA, a1s, a1d, es, ed, N);
    agg_gather4<<<GPB, TB>>>(rowoff, csrsrc, es, ed, hA, b1, Ahp, Alp, N, Mp);

    // ---------------- layer 2 (H=4, K=256) ----------------
    conv_wT<<<cdiv(256 * 256, TB), TB>>>(W2, Bhp, Blp, 256, 256, 256);
    gemm_mma<128><<<dim3(2, MT), 256, SM128>>>(Ahp, Alp, Bhp, Blp, hA, N, 256, 256);
    es_ed4<<<NPB, TB>>>(hA, a2s, a2d, es, ed, N);
    agg_gather4<<<GPB, TB>>>(rowoff, csrsrc, es, ed, hA, b2, Ahp, Alp, N, Mp);

    // ---------------- layer 3 (H=1, K=256, N=64) ----------------
    conv_wT<<<cdiv(64 * 256, TB), TB>>>(W3, Bhp, Blp, 256, 64, 256);
    gemm_mma<64><<<dim3(1, MT), 256, SM64>>>(Ahp, Alp, Bhp, Blp, h3, N, 64, 256);
    es_ed1<<<NPB, TB>>>(h3, a3s, a3d, es, ed, N);
    agg_gather1<<<NPB, TB>>>(rowoff, csrsrc, es, ed, h3, b3, Wc, bc, out, N);
}

// round 9
// speedup vs baseline: 1.2474x; 1.0718x over previous
#include <cuda_runtime.h>
#include <cuda_bf16.h>
#include <cstdint>

// ---------------------------------------------------------------------------
// SentimentGAT on GB300 (sm_103 baseline PTX): bf16x3 mma.sync GEMMs +
// CSR-gather attention; layer-1 GEMM converts fp32->bf16 hi/lo inside a
// single-barrier pipeline. Convert is SELF-CONSISTENT with the cp.async
// mapping (each thread converts only data it loaded), so cp.async.wait_group
// alone orders the convert reads -- no extra barrier needed.
// ---------------------------------------------------------------------------

#define GAT_N   30000
#define GAT_Mp  30080               // 235 * 128
#define GAT_E   480000
#define GAT_DIN 5000
#define GAT_K1P 5056                // 79 * 64 (padded K stride for W1^T)

// ---- fp32 scratch ----
__device__ float g_hA[GAT_N * 256];
__device__ float g_h3[GAT_N * 64];
__device__ float g_es[GAT_N * 4];
__device__ float g_ed[GAT_N * 4];

// ---- CSR ----
__device__ int g_rowoff[GAT_N + 1];
__device__ int g_cursor[GAT_N];
__device__ int g_csrsrc[GAT_E];

// ---- bf16 hi/lo scratch ----
__device__ __align__(128) __nv_bfloat16 g_Ah[(size_t)GAT_Mp * 256];
__device__ __align__(128) __nv_bfloat16 g_Al[(size_t)GAT_Mp * 256];
__device__ __align__(128) __nv_bfloat16 g_Bh[256 * GAT_K1P];
__device__ __align__(128) __nv_bfloat16 g_Bl[256 * GAT_K1P];

// ===========================================================================
// low-level helpers
// ===========================================================================
#define SWZ(o) ((o) ^ (((o) >> 3) & 0x70))

__device__ __forceinline__ uint32_t smem_u32(const void* p) {
    uint32_t a;
    asm("{ .reg .u64 t; cvta.to.shared.u64 t, %1; cvt.u32.u64 %0, t; }"
        : "=r"(a) : "l"(p));
    return a;
}
__device__ __forceinline__ void cp16(uint32_t d, const void* s) {
    asm volatile("cp.async.cg.shared.global [%0], [%1], 16;" :: "r"(d), "l"(s));
}
__device__ __forceinline__ void cp16z(uint32_t d, const void* s, bool pred) {
    int sz = pred ? 16 : 0;
    asm volatile("cp.async.cg.shared.global [%0], [%1], 16, %2;"
                 :: "r"(d), "l"(s), "r"(sz));
}
__device__ __forceinline__ void cp_commit() {
    asm volatile("cp.async.commit_group;" ::: "memory");
}
template <int Ng>
__device__ __forceinline__ void cp_wait() {
    asm volatile("cp.async.wait_group %0;" :: "n"(Ng) : "memory");
}
__device__ __forceinline__ void ldsm4(uint32_t (&r)[4], uint32_t addr) {
    asm volatile("ldmatrix.sync.aligned.m8n8.x4.shared.b16 {%0,%1,%2,%3}, [%4];"
                 : "=r"(r[0]), "=r"(r[1]), "=r"(r[2]), "=r"(r[3]) : "r"(addr));
}
__device__ __forceinline__ void mma16816(float (&d)[4], const uint32_t (&a)[4],
                                         uint32_t b0, uint32_t b1) {
    asm volatile("mma.sync.aligned.m16n8k16.row.col.f32.bf16.bf16.f32 "
                 "{%0,%1,%2,%3}, {%4,%5,%6,%7}, {%8,%9}, {%0,%1,%2,%3};"
                 : "+f"(d[0]), "+f"(d[1]), "+f"(d[2]), "+f"(d[3])
                 : "r"(a[0]), "r"(a[1]), "r"(a[2]), "r"(a[3]), "r"(b0), "r"(b1));
}
__device__ __forceinline__ uint32_t bfpack(float a, float b) {
    return (uint32_t)__bfloat16_as_ushort(__float2bfloat16_rn(a)) |
           ((uint32_t)__bfloat16_as_ushort(__float2bfloat16_rn(b)) << 16);
}
__device__ __forceinline__ float bfhi(float x) {
    return __bfloat162float(__float2bfloat16_rn(x));
}
__device__ __forceinline__ float sel4(float4 v, int i) {
    float a = (i & 1) ? v.y : v.x;
    float b = (i & 1) ? v.w : v.z;
    return (i & 2) ? b : a;
}

// ===========================================================================
// CSR build
// ===========================================================================
__global__ void csr_zero(int* cur, int n) {
    int i = blockIdx.x * blockDim.x + threadIdx.x;
    if (i < n) cur[i] = 0;
}
__global__ void csr_hist(const int* __restrict__ dst, int* cur, int E_) {
    int i = blockIdx.x * blockDim.x + threadIdx.x;
    if (i < E_) atomicAdd(&cur[dst[i]], 1);
}
__global__ void csr_scan(int* degcur, int* rowoff, int n) {
    __shared__ int sh[1024];
    __shared__ int carry_s;
    int tid = threadIdx.x;
    if (tid == 0) carry_s = 0;
    __syncthreads();
    for (int base = 0; base < n; base += 1024) {
        int i = base + tid;
        int v = (i < n) ? degcur[i] : 0;
        sh[tid] = v;
        __syncthreads();
#pragma unroll
        for (int o = 1; o < 1024; o <<= 1) {
            int t = (tid >= o) ? sh[tid - o] : 0;
            __syncthreads();
            sh[tid] += t;
            __syncthreads();
        }
        int excl = sh[tid] - v + carry_s;
        if (i < n) { rowoff[i] = excl; degcur[i] = excl; }
        __syncthreads();
        if (tid == 1023) carry_s += sh[1023];
        __syncthreads();
    }
    if (tid == 0) rowoff[n] = carry_s;
}
__global__ void csr_fill(const int* __restrict__ src, const int* __restrict__ dst,
                         int* cur, int* csrsrc, int E_) {
    int i = blockIdx.x * blockDim.x + threadIdx.x;
    if (i < E_) {
        int p = atomicAdd(&cur[dst[i]], 1);
        csrsrc[p] = src[i];
    }
}

// ===========================================================================
// FUSED layer-1 GEMM, single-barrier pipeline, self-consistent convert:
//   iter c: sync | mma(c) | wait loads(c+1) | convert-own(c+1) | issue(c+2)
// smem: AF 0..32K (x2 ring) | AHL 32K..64K (x2) | BHL 64K..112K (x3)
// ===========================================================================
__global__ __launch_bounds__(256)
void gemm_fused(const float* __restrict__ X,
                const __nv_bfloat16* __restrict__ Bh, const __nv_bfloat16* __restrict__ Bl,
                float* __restrict__ C, int M, int K, int KpB) {
    extern __shared__ char smem[];
    const uint32_t sb = smem_u32(smem);

    const int tid = threadIdx.x;
    const int wid = tid >> 5, lane = tid & 31;
    const int wm = wid & 3, wn = wid >> 2;
    const int bm0 = blockIdx.y * 128;
    const int bn0 = blockIdx.x * 128;

    float acc[2][8][4];
#pragma unroll
    for (int i = 0; i < 2; i++)
#pragma unroll
        for (int j = 0; j < 8; j++)
#pragma unroll
            for (int k = 0; k < 4; k++) acc[i][j][k] = 0.f;

    const int NC = (K + 31) >> 5;

    // thread i (plus t*256) owns (row = i>>3, q = i&7): used by BOTH the
    // cp.async A-load and the convert, so wait_group orders them per-thread.
    auto load_tile = [&](int c) {   // A -> AF[c%2], B -> BHL[c%3]
        const uint32_t af = sb + (c & 1) * 16384;
        const uint32_t bb = sb + 65536 + (c % 3) * 16384;
        const int k0 = c * 32;
#pragma unroll
        for (int t = 0; t < 4; t++) {
            int i = tid + t * 256;
            int row = i >> 3, q = i & 7;
            int gm = bm0 + row, gk = k0 + q * 4;
            bool p = (gm < M) && (gk < K);
            cp16z(af + row * 128 + q * 16, X + (p ? ((size_t)gm * K + gk) : 0), p);
        }
#pragma unroll
        for (int t = 0; t < 4; t++) {
            int i = tid + t * 256;
            int half = i >> 9;
            int rem = i & 511;
            int row = rem >> 2, ch = rem & 3;
            const __nv_bfloat16* src =
                (half ? Bl : Bh) + (size_t)(bn0 + row) * KpB + k0 + ch * 8;
            cp16(bb + half * 8192 + SWZ(row * 64 + ch * 16), src);
        }
    };

    auto convert = [&](int c) {     // AF[c%2] -> AHL[c%2], own data only
        const int s2 = c & 1;
        const char* afp = smem + s2 * 16384;
        char* ahp = smem + 32768 + s2 * 16384;
#pragma unroll
        for (int t = 0; t < 4; t++) {
            int i = tid + t * 256;
            int row = i >> 3, q = i & 7;
            float4 v = *(const float4*)(afp + row * 128 + q * 16);
            uint32_t h0 = bfpack(v.x, v.y);
            uint32_t h1 = bfpack(v.z, v.w);
            uint32_t l0 = bfpack(v.x - bfhi(v.x), v.y - bfhi(v.y));
            uint32_t l1 = bfpack(v.z - bfhi(v.z), v.w - bfhi(v.w));
            // 8B store inside one 16B swizzle unit
            uint32_t off = SWZ(row * 64 + (q & 6) * 8) + (q & 1) * 8;
            *(uint2*)(ahp + off)        = make_uint2(h0, h1);
            *(uint2*)(ahp + 8192 + off) = make_uint2(l0, l1);
        }
    };

    const int a_row = wm * 32 + (lane & 15);
    const int a_chb = lane >> 4;
    const int b_row = wn * 64 + ((lane >> 4) & 1) * 8 + (lane & 7);
    const int b_chb = (lane >> 3) & 1;

    // prologue
    load_tile(0); cp_commit();
    if (NC > 1) { load_tile(1); cp_commit(); }
    cp_wait<1>();            // tile 0 (own copies) complete
    convert(0);              // own data only -> no barrier needed

    for (int c = 0; c < NC; c++) {
        __syncthreads();     // publish convert(c) to all warps

        // ---- mma(c) ----
        const uint32_t aH = sb + 32768 + (c & 1) * 16384;
        const uint32_t aL = aH + 8192;
        const uint32_t bH = sb + 65536 + (c % 3) * 16384;
        const uint32_t bL = bH + 8192;
#pragma unroll
        for (int ks = 0; ks < 2; ks++) {
            uint32_t ah[2][4], al[2][4];
#pragma unroll
            for (int mf = 0; mf < 2; mf++) {
                uint32_t off = SWZ((a_row + mf * 16) * 64 + (ks * 2 + a_chb) * 16);
                ldsm4(ah[mf], aH + off);
                ldsm4(al[mf], aL + off);
            }
            uint32_t bh[4][4], bl[4][4];
#pragma unroll
            for (int p = 0; p < 4; p++) {
                uint32_t off = SWZ((b_row + p * 16) * 64 + (ks * 2 + b_chb) * 16);
                ldsm4(bh[p], bH + off);
                ldsm4(bl[p], bL + off);
            }
#pragma unroll
            for (int mf = 0; mf < 2; mf++)
#pragma unroll
                for (int p = 0; p < 4; p++) {
                    mma16816(acc[mf][2 * p],     ah[mf], bh[p][0], bh[p][1]);
                    mma16816(acc[mf][2 * p],     ah[mf], bl[p][0], bl[p][1]);
                    mma16816(acc[mf][2 * p],     al[mf], bh[p][0], bh[p][1]);
                    mma16816(acc[mf][2 * p + 1], ah[mf], bh[p][2], bh[p][3]);
                    mma16816(acc[mf][2 * p + 1], ah[mf], bl[p][2], bl[p][3]);
                    mma16816(acc[mf][2 * p + 1], al[mf], bh[p][2], bh[p][3]);
                }
        }

        // ---- convert(c+1): own cp.async data, ordered by wait_group ----
        if (c + 1 < NC) {
            cp_wait<0>();
            convert(c + 1);  // writes AHL[(c+1)%2]; mma(c) reads AHL[c%2]
        }
        // ---- prefetch tile c+2 (AF[c%2]: convert(c) done block-wide at
        //      the barrier above; BHL[(c+2)%3]: disjoint from c, c+1) ----
        if (c + 2 < NC) {
            load_tile(c + 2);
            cp_commit();
        }
    }

#pragma unroll
    for (int mf = 0; mf < 2; mf++) {
        int r0 = bm0 + wm * 32 + mf * 16 + (lane >> 2);
#pragma unroll
        for (int nf = 0; nf < 8; nf++) {
            int col = bn0 + wn * 64 + nf * 8 + (lane & 3) * 2;
            if (r0 < M)
                *(float2*)(C + (size_t)r0 * 256 + col) =
                    make_float2(acc[mf][nf][0], acc[mf][nf][1]);
            if (r0 + 8 < M)
                *(float2*)(C + (size_t)(r0 + 8) * 256 + col) =
                    make_float2(acc[mf][nf][2], acc[mf][nf][3]);
        }
    }
}

// ===========================================================================
// pre-split GEMM for layers 2/3 (proven)
// ===========================================================================
template <int BN>
__global__ __launch_bounds__(256)
void gemm_mma(const __nv_bfloat16* __restrict__ Ah, const __nv_bfloat16* __restrict__ Al,
              const __nv_bfloat16* __restrict__ Bh, const __nv_bfloat16* __restrict__ Bl,
              float* __restrict__ C, int M, int N, int Kp) {
    constexpr int WNCOL = BN / 2;
    constexpr int NFRAG = WNCOL / 8;
    constexpr int NPAIR = NFRAG / 2;
    constexpr int ABH = 8192;
    constexpr int BBH = BN * 64;
    constexpr int STAGE = 2 * ABH + 2 * BBH;

    extern __shared__ char smem[];
    const uint32_t sb = smem_u32(smem);

    const int tid = threadIdx.x;
    const int wid = tid >> 5, lane = tid & 31;
    const int wm = wid & 3, wn = wid >> 2;
    const int bm0 = blockIdx.y * 128;
    const int bn0 = blockIdx.x * BN;

    float acc[2][NFRAG][4];
#pragma unroll
    for (int i = 0; i < 2; i++)
#pragma unroll
        for (int j = 0; j < NFRAG; j++)
#pragma unroll
            for (int k = 0; k < 4; k++) acc[i][j][k] = 0.f;

    const int NC = Kp >> 5;

    auto load_stage = [&](int c, int stg) {
        const uint32_t base = sb + stg * STAGE;
        const size_t koff = (size_t)c * 32;
#pragma unroll
        for (int t = 0; t < 4; t++) {
            int i = tid + t * 256;
            int half = i >> 9;
            int rem = i & 511;
            int row = rem >> 2, ch = rem & 3;
            const __nv_bfloat16* src =
                (half ? Al : Ah) + (size_t)(bm0 + row) * Kp + koff + ch * 8;
            cp16(base + half * ABH + SWZ(row * 64 + ch * 16), src);
        }
#pragma unroll
        for (int t = 0; t < BN / 32; t++) {
            int i = tid + t * 256;
            int half = i / (BN * 4);
            int rem = i % (BN * 4);
            int row = rem >> 2, ch = rem & 3;
            const __nv_bfloat16* src =
                (half ? Bl : Bh) + (size_t)(bn0 + row) * Kp + koff + ch * 8;
            cp16(base + 2 * ABH + half * BBH + SWZ(row * 64 + ch * 16), src);
        }
    };

    const int a_row = wm * 32 + (lane & 15);
    const int a_chb = lane >> 4;
    const int b_row = wn * WNCOL + ((lane >> 4) & 1) * 8 + (lane & 7);
    const int b_chb = (lane >> 3) & 1;

    load_stage(0, 0);
    cp_commit();

    for (int c = 0; c < NC; c++) {
        if (c + 1 < NC) {
            load_stage(c + 1, (c + 1) & 1);
            cp_commit();
            cp_wait<1>();
        } else {
            cp_wait<0>();
        }
        __syncthreads();

        const uint32_t base = sb + (c & 1) * STAGE;
        const uint32_t aH = base, aL = base + ABH;
        const uint32_t bH = base + 2 * ABH, bL = bH + BBH;

#pragma unroll
        for (int ks = 0; ks < 2; ks++) {
            uint32_t ah[2][4], al[2][4];
#pragma unroll
            for (int mf = 0; mf < 2; mf++) {
                uint32_t off = SWZ((a_row + mf * 16) * 64 + (ks * 2 + a_chb) * 16);
                ldsm4(ah[mf], aH + off);
                ldsm4(al[mf], aL + off);
            }
            uint32_t bh[NPAIR][4], bl[NPAIR][4];
#pragma unroll
            for (int p = 0; p < NPAIR; p++) {
                uint32_t off = SWZ((b_row + p * 16) * 64 + (ks * 2 + b_chb) * 16);
                ldsm4(bh[p], bH + off);
                ldsm4(bl[p], bL + off);
            }
#pragma unroll
            for (int mf = 0; mf < 2; mf++)
#pragma unroll
                for (int p = 0; p < NPAIR; p++) {
                    mma16816(acc[mf][2 * p],     ah[mf], bh[p][0], bh[p][1]);
                    mma16816(acc[mf][2 * p],     ah[mf], bl[p][0], bl[p][1]);
                    mma16816(acc[mf][2 * p],     al[mf], bh[p][0], bh[p][1]);
                    mma16816(acc[mf][2 * p + 1], ah[mf], bh[p][2], bh[p][3]);
                    mma16816(acc[mf][2 * p + 1], ah[mf], bl[p][2], bl[p][3]);
                    mma16816(acc[mf][2 * p + 1], al[mf], bh[p][2], bh[p][3]);
                }
        }
        __syncthreads();
    }

#pragma unroll
    for (int mf = 0; mf < 2; mf++) {
        int r0 = bm0 + wm * 32 + mf * 16 + (lane >> 2);
#pragma unroll
        for (int nf = 0; nf < NFRAG; nf++) {
            int col = bn0 + wn * WNCOL + nf * 8 + (lane & 3) * 2;
            if (r0 < M)
                *(float2*)(C + (size_t)r0 * N + col) =
                    make_float2(acc[mf][nf][0], acc[mf][nf][1]);
            if (r0 + 8 < M)
                *(float2*)(C + (size_t)(r0 + 8) * N + col) =
                    make_float2(acc[mf][nf][2], acc[mf][nf][3]);
        }
    }
}

// ===========================================================================
// es/ed logits (one warp per node)
// ===========================================================================
__global__ void es_ed4(const float* __restrict__ h,
                       const float* __restrict__ a_src,
                       const float* __restrict__ a_dst,
                       float* __restrict__ es, float* __restrict__ ed, int n) {
    int w = (blockIdx.x * blockDim.x + threadIdx.x) >> 5;
    int lane = threadIdx.x & 31;
    if (w >= n) return;
    int c = lane * 8;
    const float* hp = h + (size_t)w * 256 + c;
    float4 v0 = *(const float4*)(hp);
    float4 v1 = *(const float4*)(hp + 4);
    float4 as0 = *(const float4*)(a_src + c);
    float4 as1 = *(const float4*)(a_src + c + 4);
    float4 ad0 = *(const float4*)(a_dst + c);
    float4 ad1 = *(const float4*)(a_dst + c + 4);
    float s = v0.x * as0.x + v0.y * as0.y + v0.z * as0.z + v0.w * as0.w +
              v1.x * as1.x + v1.y * as1.y + v1.z * as1.z + v1.w * as1.w;
    float d = v0.x * ad0.x + v0.y * ad0.y + v0.z * ad0.z + v0.w * ad0.w +
              v1.x * ad1.x + v1.y * ad1.y + v1.z * ad1.z + v1.w * ad1.w;
#pragma unroll
    for (int o = 4; o; o >>= 1) {
        s += __shfl_xor_sync(0xffffffffu, s, o);
        d += __shfl_xor_sync(0xffffffffu, d, o);
    }
    if ((lane & 7) == 0) {
        int head = lane >> 3;
        es[w * 4 + head] = s;
        ed[w * 4 + head] = d;
    }
}

__global__ void es_ed1(const float* __restrict__ h,
                       const float* __restrict__ a_src,
                       const float* __restrict__ a_dst,
                       float* __restrict__ es, float* __restrict__ ed, int n) {
    int w = (blockIdx.x * blockDim.x + threadIdx.x) >> 5;
    int lane = threadIdx.x & 31;
    if (w >= n) return;
    int c = lane * 2;
    float2 v = *(const float2*)(h + (size_t)w * 64 + c);
    float2 as = *(const float2*)(a_src + c);
    float2 ad = *(const float2*)(a_dst + c);
    float s = v.x * as.x + v.y * as.y;
    float d = v.x * ad.x + v.y * ad.y;
#pragma unroll
    for (int o = 16; o; o >>= 1) {
        s += __shfl_xor_sync(0xffffffffu, s, o);
        d += __shfl_xor_sync(0xffffffffu, d, o);
    }
    if (lane == 0) { es[w] = s; ed[w] = d; }
}

// ===========================================================================
// agg_gather4: one warp per dst node, register accumulate, fused
// normalize/bias/ELU/bf16-split (proven R7)
// ===========================================================================
__global__ void agg_gather4(const int* __restrict__ rowoff, const int* __restrict__ csrsrc,
                            const float* __restrict__ es, const float* __restrict__ ed,
                            const float* __restrict__ h, const float* __restrict__ b,
                            __nv_bfloat16* __restrict__ Hh, __nv_bfloat16* __restrict__ Hl,
                            int n, int Mp) {
    int w = (blockIdx.x * blockDim.x + threadIdx.x) >> 5;
    int lane = threadIdx.x & 31;
    if (w >= Mp) return;
    const int c0 = lane * 4;
    if (w >= n) {
        *(uint2*)(Hh + (size_t)w * 256 + c0) = make_uint2(0, 0);
        *(uint2*)(Hh + (size_t)w * 256 + c0 + 128) = make_uint2(0, 0);
        *(uint2*)(Hl + (size_t)w * 256 + c0) = make_uint2(0, 0);
        *(uint2*)(Hl + (size_t)w * 256 + c0 + 128) = make_uint2(0, 0);
        return;
    }
    const int myh = lane & 3;
    const int hs = (lane >> 4) & 1;
    float4 ed4 = *(const float4*)(ed + w * 4);
    float edh = sel4(ed4, myh);

    float4 es4 = *(const float4*)(es + w * 4);
    float e = sel4(es4, myh) + edh;
    e = e > 0.f ? e : 0.2f * e;
    float wv = __expf(e);
    float den = wv;
    float al0 = __shfl_sync(0xffffffffu, wv, hs);
    float al1 = __shfl_sync(0xffffffffu, wv, 2 + hs);

    const float* hp = h + (size_t)w * 256;
    float4 a0 = *(const float4*)(hp + c0);
    float4 a1 = *(const float4*)(hp + c0 + 128);
    a0.x *= al0; a0.y *= al0; a0.z *= al0; a0.w *= al0;
    a1.x *= al1; a1.y *= al1; a1.z *= al1; a1.w *= al1;

    int j0 = rowoff[w], j1 = rowoff[w + 1];
    int s = (j0 < j1) ? csrsrc[j0] : 0;
    for (int j = j0; j < j1; j++) {
        int snext = (j + 1 < j1) ? csrsrc[j + 1] : 0;
        float4 e4 = *(const float4*)(es + s * 4);
        float ee = sel4(e4, myh) + edh;
        ee = ee > 0.f ? ee : 0.2f * ee;
        float wj = __expf(ee);
        den += wj;
        float b0 = __shfl_sync(0xffffffffu, wj, hs);
        float b1 = __shfl_sync(0xffffffffu, wj, 2 + hs);
        const float* sp = h + (size_t)s * 256;
        float4 v0 = *(const float4*)(sp + c0);
        float4 v1 = *(const float4*)(sp + c0 + 128);
        a0.x += b0 * v0.x; a0.y += b0 * v0.y; a0.z += b0 * v0.z; a0.w += b0 * v0.w;
        a1.x += b1 * v1.x; a1.y += b1 * v1.y; a1.z += b1 * v1.z; a1.w += b1 * v1.w;
        s = snext;
    }
    float inv0 = __fdividef(1.f, __shfl_sync(0xffffffffu, den, hs));
    float inv1 = __fdividef(1.f, __shfl_sync(0xffffffffu, den, 2 + hs));

    float4 bb0 = *(const float4*)(b + c0);
    float4 bb1 = *(const float4*)(b + c0 + 128);
    float f0[4] = {a0.x * inv0 + bb0.x, a0.y * inv0 + bb0.y,
                   a0.z * inv0 + bb0.z, a0.w * inv0 + bb0.w};
    float f1[4] = {a1.x * inv1 + bb1.x, a1.y * inv1 + bb1.y,
                   a1.z * inv1 + bb1.z, a1.w * inv1 + bb1.w};
#pragma unroll
    for (int k = 0; k < 4; k++) {
        f0[k] = f0[k] > 0.f ? f0[k] : expm1f(f0[k]);
        f1[k] = f1[k] > 0.f ? f1[k] : expm1f(f1[k]);
    }
    uint32_t h0a = bfpack(f0[0], f0[1]), h0b = bfpack(f0[2], f0[3]);
    uint32_t h1a = bfpack(f1[0], f1[1]), h1b = bfpack(f1[2], f1[3]);
    float r0[4], r1[4];
#pragma unroll
    for (int k = 0; k < 4; k++) {
        r0[k] = f0[k] - bfhi(f0[k]);
        r1[k] = f1[k] - bfhi(f1[k]);
    }
    size_t o = (size_t)w * 256 + c0;
    *(uint2*)(Hh + o)       = make_uint2(h0a, h0b);
    *(uint2*)(Hh + o + 128) = make_uint2(h1a, h1b);
    *(uint2*)(Hl + o)       = make_uint2(bfpack(r0[0], r0[1]), bfpack(r0[2], r0[3]));
    *(uint2*)(Hl + o + 128) = make_uint2(bfpack(r1[0], r1[1]), bfpack(r1[2], r1[3]));
}

// ===========================================================================
// agg_gather1 + classifier (proven R7)
// ===========================================================================
__global__ void agg_gather1(const int* __restrict__ rowoff, const int* __restrict__ csrsrc,
                            const float* __restrict__ es, const float* __restrict__ ed,
                            const float* __restrict__ h, const float* __restrict__ b3,
                            const float* __restrict__ Wc, const float* __restrict__ bc,
                            float* __restrict__ out, int n) {
    int w = (blockIdx.x * blockDim.x + threadIdx.x) >> 5;
    int lane = threadIdx.x & 31;
    if (w >= n) return;
    float edw = ed[w];
    float e = es[w] + edw;
    e = e > 0.f ? e : 0.2f * e;
    float wv = __expf(e);
    float den = wv;
    float v0 = h[(size_t)w * 64 + lane] * wv;
    float v1 = h[(size_t)w * 64 + lane + 32] * wv;

    int j0 = rowoff[w], j1 = rowoff[w + 1];
    int s = (j0 < j1) ? csrsrc[j0] : 0;
    for (int j = j0; j < j1; j++) {
        int snext = (j + 1 < j1) ? csrsrc[j + 1] : 0;
        float ee = es[s] + edw;
        ee = ee > 0.f ? ee : 0.2f * ee;
        float wj = __expf(ee);
        den += wj;
        v0 += wj * h[(size_t)s * 64 + lane];
        v1 += wj * h[(size_t)s * 64 + lane + 32];
        s = snext;
    }
    float inv = __fdividef(1.f, den);
    v0 = v0 * inv + b3[lane];
    v0 = v0 > 0.f ? v0 : expm1f(v0);
    v1 = v1 * inv + b3[lane + 32];
    v1 = v1 > 0.f ? v1 : expm1f(v1);
#pragma unroll
    for (int j = 0; j < 3; j++) {
        float p = v0 * Wc[lane * 3 + j] + v1 * Wc[(lane + 32) * 3 + j];
#pragma unroll
        for (int o = 16; o; o >>= 1) p += __shfl_xor_sync(0xffffffffu, p, o);
        if (lane == 0) out[w * 3 + j] = p + bc[j];
    }
}

// ===========================================================================
// W [K,N] fp32 -> hi/lo bf16 [N,Kp]
// ===========================================================================
__global__ void conv_wT(const float* __restrict__ W,
                        __nv_bfloat16* __restrict__ Bh,
                        __nv_bfloat16* __restrict__ Bl,
                        int K, int N, int Kp) {
    int idx = blockIdx.x * blockDim.x + threadIdx.x;
    if (idx >= N * Kp) return;
    int n = idx / Kp, k = idx - n * Kp;
    float v = (k < K) ? W[(size_t)k * N + n] : 0.f;
    __nv_bfloat16 h = __float2bfloat16_rn(v);
    __nv_bfloat16 l = __float2bfloat16_rn(v - __bfloat162float(h));
    Bh[(size_t)n * Kp + k] = h;
    Bl[(size_t)n * Kp + k] = l;
}

// ===========================================================================
static inline int cdiv(int a, int b) { return (a + b - 1) / b; }

extern "C" void kernel_launch(void* const* d_in, const int* in_sizes, int n_in,
                              void* d_out, int out_size) {
    const float* x    = (const float*)d_in[0];
    const float* W1   = (const float*)d_in[1];
    const float* a1s  = (const float*)d_in[2];
    const float* a1d  = (const float*)d_in[3];
    const float* b1   = (const float*)d_in[4];
    const float* W2   = (const float*)d_in[5];
    const float* a2s  = (const float*)d_in[6];
    const float* a2d  = (const float*)d_in[7];
    const float* b2   = (const float*)d_in[8];
    const float* W3   = (const float*)d_in[9];
    const float* a3s  = (const float*)d_in[10];
    const float* a3d  = (const float*)d_in[11];
    const float* b3   = (const float*)d_in[12];
    const float* Wc   = (const float*)d_in[13];
    const float* bc   = (const float*)d_in[14];
    const int*   ei   = (const int*)d_in[15];
    float* out = (float*)d_out;

    const int N = GAT_N, E = GAT_E, Mp = GAT_Mp;
    const int* src = ei;
    const int* dst = ei + E;

    float *hA, *h3, *es, *ed;
    int *rowoff, *cursor, *csrsrc;
    __nv_bfloat16 *Ahp, *Alp, *Bhp, *Blp;
    cudaGetSymbolAddress((void**)&hA,     g_hA);
    cudaGetSymbolAddress((void**)&h3,     g_h3);
    cudaGetSymbolAddress((void**)&es,     g_es);
    cudaGetSymbolAddress((void**)&ed,     g_ed);
    cudaGetSymbolAddress((void**)&rowoff, g_rowoff);
    cudaGetSymbolAddress((void**)&cursor, g_cursor);
    cudaGetSymbolAddress((void**)&csrsrc, g_csrsrc);
    cudaGetSymbolAddress((void**)&Ahp,    g_Ah);
    cudaGetSymbolAddress((void**)&Alp,    g_Al);
    cudaGetSymbolAddress((void**)&Bhp,    g_Bh);
    cudaGetSymbolAddress((void**)&Blp,    g_Bl);

    const int SMF   = 114688;                          // AF 32K + AHL 32K + BHL 48K
    const int SM128 = 2 * (2 * 8192 + 2 * 128 * 64);
    const int SM64  = 2 * (2 * 8192 + 2 * 64 * 64);
    cudaFuncSetAttribute(gemm_fused,    cudaFuncAttributeMaxDynamicSharedMemorySize, SMF);
    cudaFuncSetAttribute(gemm_mma<128>, cudaFuncAttributeMaxDynamicSharedMemorySize, SM128);
    cudaFuncSetAttribute(gemm_mma<64>,  cudaFuncAttributeMaxDynamicSharedMemorySize, SM64);

    const int TB = 256;
    const int MT = Mp / 128;               // 235
    const int NPB = cdiv(N * 32, TB);      // warp-per-node blocks
    const int GPB = cdiv(Mp * 32, TB);     // warp-per-padded-node blocks

    // ---------------- CSR build ----------------
    csr_zero<<<cdiv(N, TB), TB>>>(cursor, N);
    csr_hist<<<cdiv(E, TB), TB>>>(dst, cursor, E);
    csr_scan<<<1, 1024>>>(cursor, rowoff, N);
    csr_fill<<<cdiv(E, TB), TB>>>(src, dst, cursor, csrsrc, E);

    // ---------------- layer 1 (H=4, K=5000) ----------------
    conv_wT<<<cdiv(256 * GAT_K1P, TB), TB>>>(W1, Bhp, Blp, GAT_DIN, 256, GAT_K1P);
    gemm_fused<<<dim3(2, MT), 256, SMF>>>(x, Bhp, Blp, hA, N, GAT_DIN, GAT_K1P);
    es_ed4<<<NPB, TB>>>(hA, a1s, a1d, es, ed, N);
    agg_gather4<<<GPB, TB>>>(rowoff, csrsrc, es, ed, hA, b1, Ahp, Alp, N, Mp);

    // ---------------- layer 2 (H=4, K=256) ----------------
    conv_wT<<<cdiv(256 * 256, TB), TB>>>(W2, Bhp, Blp, 256, 256, 256);
    gemm_mma<128><<<dim3(2, MT), 256, SM128>>>(Ahp, Alp, Bhp, Blp, hA, N, 256, 256);
    es_ed4<<<NPB, TB>>>(hA, a2s, a2d, es, ed, N);
    agg_gather4<<<GPB, TB>>>(rowoff, csrsrc, es, ed, hA, b2, Ahp, Alp, N, Mp);

    // ---------------- layer 3 (H=1, K=256, N=64) ----------------
    conv_wT<<<cdiv(64 * 256, TB), TB>>>(W3, Bhp, Blp, 256, 64, 256);
    gemm_mma<64><<<dim3(1, MT), 256, SM64>>>(Ahp, Alp, Bhp, Blp, h3, N, 64, 256);
    es_ed1<<<NPB, TB>>>(h3, a3s, a3d, es, ed, N);
    agg_gather1<<<NPB, TB>>>(rowoff, csrsrc, es, ed, h3, b3, Wc, bc, out, N);
}